// round 2
// baseline (speedup 1.0000x reference)
#include <cuda_runtime.h>
#include <math.h>

#define NN 50000
#define EE 1600000
#define DD 128
#define ET (EE + NN)

typedef unsigned long long u64;

// ---------------- scratch (static device globals; no allocation) ------------
__device__ float g_bufA[NN * DD];   // layer input (expmap0(x), then activations)
__device__ float g_bufH[NN * DD];   // h = A @ W
__device__ float g_s[NN];           // h . a_src
__device__ float g_d[NN];           // h . a_dst
__device__ float g_e[ET];           // per-edge raw attention logit (CSR order)
__device__ int   g_count[NN];
__device__ int   g_rowptr[NN + 1];
__device__ int   g_cursor[NN];
__device__ int   g_col[ET];         // CSR (by dst) source indices

// ---------------- f32x2 helpers ----------------------------------------------
__device__ __forceinline__ u64 pk2(float x, float y) {
    u64 r; asm("mov.b64 %0, {%1, %2};" : "=l"(r) : "f"(x), "f"(y)); return r;
}
__device__ __forceinline__ void fma2(u64& d, u64 a, u64 b) {
    asm("fma.rn.f32x2 %0, %1, %2, %0;" : "+l"(d) : "l"(a), "l"(b));
}
__device__ __forceinline__ float2 upk(u64 v) {
    float2 f; asm("mov.b64 {%0, %1}, %2;" : "=f"(f.x), "=f"(f.y) : "l"(v)); return f;
}

// ---------------- CSR build --------------------------------------------------
__global__ void init_count_kernel() {
    int i = blockIdx.x * blockDim.x + threadIdx.x;
    if (i < NN) g_count[i] = 1;   // self loop contributes 1 to every node
}

__global__ void hist_kernel(const int* __restrict__ dst) {
    int i = blockIdx.x * blockDim.x + threadIdx.x;
    if (i < EE) atomicAdd(&g_count[dst[i]], 1);
}

// single-block exclusive scan over g_count -> g_rowptr, g_cursor
__global__ void scan_kernel() {
    __shared__ int wsum[32];
    __shared__ int off;
    int tid = threadIdx.x, lane = tid & 31, wid = tid >> 5;
    if (tid == 0) off = 0;
    __syncthreads();
    for (int base = 0; base < NN; base += 1024) {
        int i = base + tid;
        int v = (i < NN) ? g_count[i] : 0;
        int x = v;
        #pragma unroll
        for (int o = 1; o < 32; o <<= 1) {
            int y = __shfl_up_sync(0xffffffffu, x, o);
            if (lane >= o) x += y;
        }
        if (lane == 31) wsum[wid] = x;
        __syncthreads();
        if (wid == 0) {
            int w = wsum[lane];
            int xx = w;
            #pragma unroll
            for (int o = 1; o < 32; o <<= 1) {
                int y = __shfl_up_sync(0xffffffffu, xx, o);
                if (lane >= o) xx += y;
            }
            wsum[lane] = xx - w;
        }
        __syncthreads();
        int incl = x + wsum[wid];
        int excl = incl - v + off;
        if (i < NN) { g_rowptr[i] = excl; g_cursor[i] = excl; }
        __syncthreads();
        if (tid == 1023) off += incl;
        __syncthreads();
    }
    if (threadIdx.x == 0) g_rowptr[NN] = off;
}

__global__ void scatter_kernel(const int* __restrict__ src, const int* __restrict__ dst) {
    int i = blockIdx.x * blockDim.x + threadIdx.x;
    if (i >= ET) return;
    int s, t;
    if (i < EE) { s = src[i]; t = dst[i]; }
    else        { s = i - EE; t = s; }           // self loops
    int pos = atomicAdd(&g_cursor[t], 1);
    g_col[pos] = s;
}

// ---------------- expmap0 ----------------------------------------------------
__global__ void expmap_kernel(const float* __restrict__ x) {
    int gid = blockIdx.x * blockDim.x + threadIdx.x;
    int row = gid >> 5, lane = gid & 31;
    if (row >= NN) return;
    float4 v = ((const float4*)x)[row * 32 + lane];
    float ss = v.x * v.x + v.y * v.y + v.z * v.z + v.w * v.w;
    #pragma unroll
    for (int o = 16; o; o >>= 1) ss += __shfl_xor_sync(0xffffffffu, ss, o);
    float n = sqrtf(ss);
    n = fmaxf(n, 1e-15f);
    float sc = tanhf(n) / n;
    v.x *= sc; v.y *= sc; v.z *= sc; v.w *= sc;
    ((float4*)g_bufA)[row * 32 + lane] = v;
}

// ---------------- GEMM: H = A @ W via fma.rn.f32x2, fused s/d epilogue -------
// block: 256 threads (8 warps), tile 64 rows x 128 cols. Each warp: 8 rows.
// k paired even/odd into dual accumulators (f32x2 lanes), summed at the end.
__global__ void gemm_kernel(const float* __restrict__ A, const float* __restrict__ W,
                            const float* __restrict__ avs, const float* __restrict__ avd) {
    extern __shared__ float sm[];
    float* Ws = sm;              // [128][128]
    float* As = sm + 128 * 128;  // [64][128]
    int tid = threadIdx.x;
    int row0 = blockIdx.x * 64;

    for (int i = tid; i < (128 * 128) / 4; i += 256)
        ((float4*)Ws)[i] = ((const float4*)W)[i];
    for (int i = tid; i < (64 * 128) / 4; i += 256) {
        int r = i >> 5, c4 = i & 31;
        int row = row0 + r;
        float4 v = (row < NN) ? ((const float4*)A)[row * 32 + c4]
                              : make_float4(0.f, 0.f, 0.f, 0.f);
        ((float4*)As)[i] = v;
    }
    __syncthreads();

    int w = tid >> 5, lane = tid & 31;
    int r0 = w * 8;          // 8 rows per warp
    int c0 = lane * 4;       // 4 cols per lane

    u64 acc[8][4];
    #pragma unroll
    for (int i = 0; i < 8; i++)
        #pragma unroll
        for (int j = 0; j < 4; j++) acc[i][j] = 0ull;

    #pragma unroll 2
    for (int k = 0; k < 128; k += 2) {
        float4 w0 = *(const float4*)&Ws[k * 128 + c0];
        float4 w1 = *(const float4*)&Ws[(k + 1) * 128 + c0];
        u64 b0 = pk2(w0.x, w1.x);
        u64 b1 = pk2(w0.y, w1.y);
        u64 b2 = pk2(w0.z, w1.z);
        u64 b3 = pk2(w0.w, w1.w);
        #pragma unroll
        for (int i = 0; i < 8; i++) {
            u64 a2 = *(const u64*)&As[(r0 + i) * 128 + k];   // broadcast (A[k],A[k+1])
            fma2(acc[i][0], a2, b0);
            fma2(acc[i][1], a2, b1);
            fma2(acc[i][2], a2, b2);
            fma2(acc[i][3], a2, b3);
        }
    }

    float4 asv = *(const float4*)&avs[c0];
    float4 adv = *(const float4*)&avd[c0];
    #pragma unroll
    for (int i = 0; i < 8; i++) {
        int row = row0 + r0 + i;
        if (row < NN) {   // uniform across warp
            float2 p0 = upk(acc[i][0]);
            float2 p1 = upk(acc[i][1]);
            float2 p2 = upk(acc[i][2]);
            float2 p3 = upk(acc[i][3]);
            float4 o;
            o.x = p0.x + p0.y; o.y = p1.x + p1.y;
            o.z = p2.x + p2.y; o.w = p3.x + p3.y;
            ((float4*)g_bufH)[row * 32 + lane] = o;
            float ps = o.x * asv.x + o.y * asv.y + o.z * asv.z + o.w * asv.w;
            float pd = o.x * adv.x + o.y * adv.y + o.z * adv.z + o.w * adv.w;
            #pragma unroll
            for (int off = 16; off; off >>= 1) {
                ps += __shfl_xor_sync(0xffffffffu, ps, off);
                pd += __shfl_xor_sync(0xffffffffu, pd, off);
            }
            if (lane == 0) { g_s[row] = ps; g_d[row] = pd; }
        }
    }
}

// ---------------- per-node attention aggregation (1 warp / node) -------------
__global__ void agg_kernel(const float* __restrict__ H, const float* __restrict__ sarr,
                           const float* __restrict__ darr, const float* __restrict__ bias,
                           float* __restrict__ out, int act) {
    __shared__ float ebuf[8][128];
    int lane = threadIdx.x & 31, ws = threadIdx.x >> 5;
    int node = (blockIdx.x * blockDim.x + threadIdx.x) >> 5;
    if (node >= NN) return;

    int beg = g_rowptr[node], end = g_rowptr[node + 1];
    float di = darr[node];

    // pass 1: online softmax; stash raw logits (CSR-sequential, coalesced)
    float m = -1e30f, den = 0.f;
    for (int j = beg + lane; j < end; j += 32) {
        float e = sarr[g_col[j]] + di;
        e = e > 0.f ? e : 0.2f * e;
        g_e[j] = e;
        float nm = fmaxf(m, e);
        den = den * __expf(m - nm) + __expf(e - nm);
        m = nm;
    }
    #pragma unroll
    for (int o = 16; o; o >>= 1) {
        float m2 = __shfl_xor_sync(0xffffffffu, m, o);
        float d2 = __shfl_xor_sync(0xffffffffu, den, o);
        float nm = fmaxf(m, m2);
        den = den * __expf(m - nm) + d2 * __expf(m2 - nm);
        m = nm;
    }
    float inv = 1.f / den;

    // pass 2: weighted gather-accumulate (alpha staged in smem per warp)
    float4 acc = make_float4(0.f, 0.f, 0.f, 0.f);
    for (int cb = beg; cb < end; cb += 128) {
        int cn = min(128, end - cb);
        for (int j = lane; j < cn; j += 32) {
            float e = g_e[cb + j];               // sequential re-read
            ebuf[ws][j] = __expf(e - m) * inv;
        }
        __syncwarp();
        #pragma unroll 4
        for (int j = 0; j < cn; j++) {
            int sn = g_col[cb + j];              // broadcast load
            float al = ebuf[ws][j];
            float4 hv = ((const float4*)H)[sn * 32 + lane];  // L2-resident gather
            acc.x = fmaf(al, hv.x, acc.x);
            acc.y = fmaf(al, hv.y, acc.y);
            acc.z = fmaf(al, hv.z, acc.z);
            acc.w = fmaf(al, hv.w, acc.w);
        }
        __syncwarp();
    }

    float4 bv = ((const float4*)bias)[lane];
    acc.x += bv.x; acc.y += bv.y; acc.z += bv.z; acc.w += bv.w;
    if (act) {
        acc.x = 2.f * tanhf(acc.x);
        acc.y = 2.f * tanhf(acc.y);
        acc.z = 2.f * tanhf(acc.z);
        acc.w = 2.f * tanhf(acc.w);
    }
    ((float4*)out)[node * 32 + lane] = acc;
}

// ---------------- launch ------------------------------------------------------
extern "C" void kernel_launch(void* const* d_in, const int* in_sizes, int n_in,
                              void* d_out, int out_size) {
    const float* x   = (const float*)d_in[0];
    const int*   ei  = (const int*)d_in[1];
    const int*   esrc = ei;
    const int*   edst = ei + EE;
    const float* W1  = (const float*)d_in[2];
    const float* a1s = (const float*)d_in[3];
    const float* a1d = (const float*)d_in[4];
    const float* b1  = (const float*)d_in[5];
    const float* W2  = (const float*)d_in[6];
    const float* a2s = (const float*)d_in[7];
    const float* a2d = (const float*)d_in[8];
    const float* b2  = (const float*)d_in[9];
    const float* W3  = (const float*)d_in[10];
    const float* a3s = (const float*)d_in[11];
    const float* a3d = (const float*)d_in[12];
    const float* b3  = (const float*)d_in[13];
    float* out = (float*)d_out;

    float *pA, *pH, *pS, *pD;
    cudaGetSymbolAddress((void**)&pA, g_bufA);
    cudaGetSymbolAddress((void**)&pH, g_bufH);
    cudaGetSymbolAddress((void**)&pS, g_s);
    cudaGetSymbolAddress((void**)&pD, g_d);

    const int SMEM = (128 * 128 + 64 * 128) * 4;   // 98304 B
    cudaFuncSetAttribute(gemm_kernel, cudaFuncAttributeMaxDynamicSharedMemorySize, SMEM);

    // CSR build (once per launch)
    init_count_kernel<<<(NN + 255) / 256, 256>>>();
    hist_kernel<<<(EE + 255) / 256, 256>>>(edst);
    scan_kernel<<<1, 1024>>>();
    scatter_kernel<<<(ET + 255) / 256, 256>>>(esrc, edst);

    // expmap0
    expmap_kernel<<<(NN * 32 + 255) / 256, 256>>>(x);

    int gemm_blocks = (NN + 63) / 64;
    int agg_blocks  = (NN + 7) / 8;

    // layer 1
    gemm_kernel<<<gemm_blocks, 256, SMEM>>>(pA, W1, a1s, a1d);
    agg_kernel<<<agg_blocks, 256>>>(pH, pS, pD, b1, pA, 1);
    // layer 2
    gemm_kernel<<<gemm_blocks, 256, SMEM>>>(pA, W2, a2s, a2d);
    agg_kernel<<<agg_blocks, 256>>>(pH, pS, pD, b2, pA, 1);
    // layer 3
    gemm_kernel<<<gemm_blocks, 256, SMEM>>>(pA, W3, a3s, a3d);
    agg_kernel<<<agg_blocks, 256>>>(pH, pS, pD, b3, out, 0);
}

// round 3
// speedup vs baseline: 1.0298x; 1.0298x over previous
#include <cuda_runtime.h>
#include <math.h>

#define NN 50000
#define EE 1600000
#define DD 128
#define ET (EE + NN)

// ---------------- scratch (static device globals; no allocation) ------------
__device__ float g_bufA[NN * DD];   // layer input (expmap0(x), then activations)
__device__ float g_bufH[NN * DD];   // h = A @ W
__device__ float g_s[NN];           // h . a_src
__device__ float g_d[NN];           // h . a_dst
__device__ float g_e[ET];           // per-edge raw attention logit (CSR order)
__device__ int   g_count[NN];
__device__ int   g_rowptr[NN + 1];
__device__ int   g_cursor[NN];
__device__ int   g_col[ET];         // CSR (by dst) source indices

// ---------------- CSR build --------------------------------------------------
__global__ void init_count_kernel() {
    int i = blockIdx.x * blockDim.x + threadIdx.x;
    if (i < NN) g_count[i] = 1;   // self loop contributes 1 to every node
}

__global__ void hist_kernel(const int* __restrict__ dst) {
    int i = blockIdx.x * blockDim.x + threadIdx.x;
    if (i < EE) atomicAdd(&g_count[dst[i]], 1);
}

// single-block exclusive scan over g_count -> g_rowptr, g_cursor
__global__ void scan_kernel() {
    __shared__ int wsum[32];
    __shared__ int off;
    int tid = threadIdx.x, lane = tid & 31, wid = tid >> 5;
    if (tid == 0) off = 0;
    __syncthreads();
    for (int base = 0; base < NN; base += 1024) {
        int i = base + tid;
        int v = (i < NN) ? g_count[i] : 0;
        int x = v;
        #pragma unroll
        for (int o = 1; o < 32; o <<= 1) {
            int y = __shfl_up_sync(0xffffffffu, x, o);
            if (lane >= o) x += y;
        }
        if (lane == 31) wsum[wid] = x;
        __syncthreads();
        if (wid == 0) {
            int w = wsum[lane];
            int xx = w;
            #pragma unroll
            for (int o = 1; o < 32; o <<= 1) {
                int y = __shfl_up_sync(0xffffffffu, xx, o);
                if (lane >= o) xx += y;
            }
            wsum[lane] = xx - w;
        }
        __syncthreads();
        int incl = x + wsum[wid];
        int excl = incl - v + off;
        if (i < NN) { g_rowptr[i] = excl; g_cursor[i] = excl; }
        __syncthreads();
        if (tid == 1023) off += incl;
        __syncthreads();
    }
    if (threadIdx.x == 0) g_rowptr[NN] = off;
}

__global__ void scatter_kernel(const int* __restrict__ src, const int* __restrict__ dst) {
    int i = blockIdx.x * blockDim.x + threadIdx.x;
    if (i >= ET) return;
    int s, t;
    if (i < EE) { s = src[i]; t = dst[i]; }
    else        { s = i - EE; t = s; }           // self loops
    int pos = atomicAdd(&g_cursor[t], 1);
    g_col[pos] = s;
}

// ---------------- expmap0 ----------------------------------------------------
__global__ void expmap_kernel(const float* __restrict__ x) {
    int gid = blockIdx.x * blockDim.x + threadIdx.x;
    int row = gid >> 5, lane = gid & 31;
    if (row >= NN) return;
    float4 v = ((const float4*)x)[row * 32 + lane];
    float ss = v.x * v.x + v.y * v.y + v.z * v.z + v.w * v.w;
    #pragma unroll
    for (int o = 16; o; o >>= 1) ss += __shfl_xor_sync(0xffffffffu, ss, o);
    float n = sqrtf(ss);
    n = fmaxf(n, 1e-15f);
    float sc = tanhf(n) / n;
    v.x *= sc; v.y *= sc; v.z *= sc; v.w *= sc;
    ((float4*)g_bufA)[row * 32 + lane] = v;
}

// ---------------- GEMM: H = A @ W, fused s/d epilogue ------------------------
// block: 128 threads (4 warps), tile 64 rows x 128 cols. Warp: 16 rows.
// k blocked by 4: A read as float4 broadcast, W as 4x float4 -> 8% issue overhead.
__global__ void gemm_kernel(const float* __restrict__ A, const float* __restrict__ W,
                            const float* __restrict__ avs, const float* __restrict__ avd) {
    extern __shared__ float sm[];
    float* Ws = sm;              // [128][128]
    float* As = sm + 128 * 128;  // [64][128]
    int tid = threadIdx.x;
    int row0 = blockIdx.x * 64;

    for (int i = tid; i < (128 * 128) / 4; i += 128)
        ((float4*)Ws)[i] = ((const float4*)W)[i];
    for (int i = tid; i < (64 * 128) / 4; i += 128) {
        int r = i >> 5, c4 = i & 31;
        int row = row0 + r;
        float4 v = (row < NN) ? ((const float4*)A)[row * 32 + c4]
                              : make_float4(0.f, 0.f, 0.f, 0.f);
        ((float4*)As)[i] = v;
    }
    __syncthreads();

    int w = tid >> 5, lane = tid & 31;
    int r0 = w * 16;        // 16 rows per warp (lanes share rows -> smem broadcast)
    int c0 = lane * 4;      // 4 cols per lane

    float acc[16][4];
    #pragma unroll
    for (int i = 0; i < 16; i++)
        #pragma unroll
        for (int j = 0; j < 4; j++) acc[i][j] = 0.f;

    for (int k0 = 0; k0 < 128; k0 += 4) {
        float4 w0 = *(const float4*)&Ws[(k0 + 0) * 128 + c0];
        float4 w1 = *(const float4*)&Ws[(k0 + 1) * 128 + c0];
        float4 w2 = *(const float4*)&Ws[(k0 + 2) * 128 + c0];
        float4 w3 = *(const float4*)&Ws[(k0 + 3) * 128 + c0];
        #pragma unroll
        for (int i = 0; i < 16; i++) {
            float4 av = *(const float4*)&As[(r0 + i) * 128 + k0];  // broadcast LDS.128
            acc[i][0] = fmaf(av.x, w0.x, acc[i][0]);
            acc[i][1] = fmaf(av.x, w0.y, acc[i][1]);
            acc[i][2] = fmaf(av.x, w0.z, acc[i][2]);
            acc[i][3] = fmaf(av.x, w0.w, acc[i][3]);
            acc[i][0] = fmaf(av.y, w1.x, acc[i][0]);
            acc[i][1] = fmaf(av.y, w1.y, acc[i][1]);
            acc[i][2] = fmaf(av.y, w1.z, acc[i][2]);
            acc[i][3] = fmaf(av.y, w1.w, acc[i][3]);
            acc[i][0] = fmaf(av.z, w2.x, acc[i][0]);
            acc[i][1] = fmaf(av.z, w2.y, acc[i][1]);
            acc[i][2] = fmaf(av.z, w2.z, acc[i][2]);
            acc[i][3] = fmaf(av.z, w2.w, acc[i][3]);
            acc[i][0] = fmaf(av.w, w3.x, acc[i][0]);
            acc[i][1] = fmaf(av.w, w3.y, acc[i][1]);
            acc[i][2] = fmaf(av.w, w3.z, acc[i][2]);
            acc[i][3] = fmaf(av.w, w3.w, acc[i][3]);
        }
    }

    float4 asv = *(const float4*)&avs[c0];
    float4 adv = *(const float4*)&avd[c0];
    #pragma unroll
    for (int i = 0; i < 16; i++) {
        int row = row0 + r0 + i;
        if (row < NN) {   // uniform across warp
            float4 o;
            o.x = acc[i][0]; o.y = acc[i][1]; o.z = acc[i][2]; o.w = acc[i][3];
            ((float4*)g_bufH)[row * 32 + lane] = o;
            float ps = o.x * asv.x + o.y * asv.y + o.z * asv.z + o.w * asv.w;
            float pd = o.x * adv.x + o.y * adv.y + o.z * adv.z + o.w * adv.w;
            #pragma unroll
            for (int off = 16; off; off >>= 1) {
                ps += __shfl_xor_sync(0xffffffffu, ps, off);
                pd += __shfl_xor_sync(0xffffffffu, pd, off);
            }
            if (lane == 0) { g_s[row] = ps; g_d[row] = pd; }
        }
    }
}

// ---------------- per-node attention aggregation (1 warp / node) -------------
__global__ void agg_kernel(const float* __restrict__ H, const float* __restrict__ sarr,
                           const float* __restrict__ darr, const float* __restrict__ bias,
                           float* __restrict__ out, int act) {
    __shared__ float ebuf[8][128];
    int lane = threadIdx.x & 31, ws = threadIdx.x >> 5;
    int node = (blockIdx.x * blockDim.x + threadIdx.x) >> 5;
    if (node >= NN) return;

    int beg = g_rowptr[node], end = g_rowptr[node + 1];
    float di = darr[node];

    // pass 1: online softmax; stash raw logits (CSR-sequential, coalesced)
    float m = -1e30f, den = 0.f;
    for (int j = beg + lane; j < end; j += 32) {
        float e = sarr[g_col[j]] + di;
        e = e > 0.f ? e : 0.2f * e;
        g_e[j] = e;
        float nm = fmaxf(m, e);
        den = den * __expf(m - nm) + __expf(e - nm);
        m = nm;
    }
    #pragma unroll
    for (int o = 16; o; o >>= 1) {
        float m2 = __shfl_xor_sync(0xffffffffu, m, o);
        float d2 = __shfl_xor_sync(0xffffffffu, den, o);
        float nm = fmaxf(m, m2);
        den = den * __expf(m - nm) + d2 * __expf(m2 - nm);
        m = nm;
    }
    float inv = 1.f / den;

    // pass 2: weighted gather-accumulate (alpha staged in smem per warp)
    float4 acc = make_float4(0.f, 0.f, 0.f, 0.f);
    for (int cb = beg; cb < end; cb += 128) {
        int cn = min(128, end - cb);
        for (int j = lane; j < cn; j += 32) {
            float e = g_e[cb + j];               // sequential re-read
            ebuf[ws][j] = __expf(e - m) * inv;
        }
        __syncwarp();
        #pragma unroll 4
        for (int j = 0; j < cn; j++) {
            int sn = g_col[cb + j];              // broadcast load
            float al = ebuf[ws][j];
            float4 hv = ((const float4*)H)[sn * 32 + lane];  // L2-resident gather
            acc.x = fmaf(al, hv.x, acc.x);
            acc.y = fmaf(al, hv.y, acc.y);
            acc.z = fmaf(al, hv.z, acc.z);
            acc.w = fmaf(al, hv.w, acc.w);
        }
        __syncwarp();
    }

    float4 bv = ((const float4*)bias)[lane];
    acc.x += bv.x; acc.y += bv.y; acc.z += bv.z; acc.w += bv.w;
    if (act) {
        acc.x = 2.f * tanhf(acc.x);
        acc.y = 2.f * tanhf(acc.y);
        acc.z = 2.f * tanhf(acc.z);
        acc.w = 2.f * tanhf(acc.w);
    }
    ((float4*)out)[node * 32 + lane] = acc;
}

// ---------------- launch ------------------------------------------------------
extern "C" void kernel_launch(void* const* d_in, const int* in_sizes, int n_in,
                              void* d_out, int out_size) {
    const float* x   = (const float*)d_in[0];
    const int*   ei  = (const int*)d_in[1];
    const int*   esrc = ei;
    const int*   edst = ei + EE;
    const float* W1  = (const float*)d_in[2];
    const float* a1s = (const float*)d_in[3];
    const float* a1d = (const float*)d_in[4];
    const float* b1  = (const float*)d_in[5];
    const float* W2  = (const float*)d_in[6];
    const float* a2s = (const float*)d_in[7];
    const float* a2d = (const float*)d_in[8];
    const float* b2  = (const float*)d_in[9];
    const float* W3  = (const float*)d_in[10];
    const float* a3s = (const float*)d_in[11];
    const float* a3d = (const float*)d_in[12];
    const float* b3  = (const float*)d_in[13];
    float* out = (float*)d_out;

    float *pA, *pH, *pS, *pD;
    cudaGetSymbolAddress((void**)&pA, g_bufA);
    cudaGetSymbolAddress((void**)&pH, g_bufH);
    cudaGetSymbolAddress((void**)&pS, g_s);
    cudaGetSymbolAddress((void**)&pD, g_d);

    const int SMEM = (128 * 128 + 64 * 128) * 4;   // 98304 B
    cudaFuncSetAttribute(gemm_kernel, cudaFuncAttributeMaxDynamicSharedMemorySize, SMEM);

    // CSR build (once per launch)
    init_count_kernel<<<(NN + 255) / 256, 256>>>();
    hist_kernel<<<(EE + 255) / 256, 256>>>(edst);
    scan_kernel<<<1, 1024>>>();
    scatter_kernel<<<(ET + 255) / 256, 256>>>(esrc, edst);

    // expmap0
    expmap_kernel<<<(NN * 32 + 255) / 256, 256>>>(x);

    int gemm_blocks = (NN + 63) / 64;
    int agg_blocks  = (NN + 7) / 8;

    // layer 1
    gemm_kernel<<<gemm_blocks, 128, SMEM>>>(pA, W1, a1s, a1d);
    agg_kernel<<<agg_blocks, 256>>>(pH, pS, pD, b1, pA, 1);
    // layer 2
    gemm_kernel<<<gemm_blocks, 128, SMEM>>>(pA, W2, a2s, a2d);
    agg_kernel<<<agg_blocks, 256>>>(pH, pS, pD, b2, pA, 1);
    // layer 3
    gemm_kernel<<<gemm_blocks, 128, SMEM>>>(pA, W3, a3s, a3d);
    agg_kernel<<<agg_blocks, 256>>>(pH, pS, pD, b3, out, 0);
}

// round 4
// speedup vs baseline: 1.1921x; 1.1575x over previous
#include <cuda_runtime.h>
#include <cuda_fp16.h>
#include <math.h>

#define NN 50000
#define EE 1600000
#define DD 128
#define ET (EE + NN)

// ---------------- scratch (static device globals; no allocation) ------------
__device__ float  g_bufA[NN * DD];   // layer input (expmap0(x), then activations)
__device__ __half g_bufH[NN * DD];   // h = A @ W (fp16 for the gather)
__device__ float  g_s[NN];           // h . a_src
__device__ float  g_d[NN];           // h . a_dst
__device__ int    g_count[NN];
__device__ int    g_rowptr[NN + 1];
__device__ int    g_cursor[NN];
__device__ int    g_col[ET];         // CSR (by dst) source indices

// ---------------- CSR build --------------------------------------------------
__global__ void init_count_kernel() {
    int i = blockIdx.x * blockDim.x + threadIdx.x;
    if (i < NN) g_count[i] = 1;   // self loop contributes 1 to every node
}

__global__ void hist_kernel(const int* __restrict__ dst) {
    int i = blockIdx.x * blockDim.x + threadIdx.x;
    if (i < EE) atomicAdd(&g_count[dst[i]], 1);
}

// single-block exclusive scan over g_count -> g_rowptr, g_cursor
__global__ void scan_kernel() {
    __shared__ int wsum[32];
    __shared__ int off;
    int tid = threadIdx.x, lane = tid & 31, wid = tid >> 5;
    if (tid == 0) off = 0;
    __syncthreads();
    for (int base = 0; base < NN; base += 1024) {
        int i = base + tid;
        int v = (i < NN) ? g_count[i] : 0;
        int x = v;
        #pragma unroll
        for (int o = 1; o < 32; o <<= 1) {
            int y = __shfl_up_sync(0xffffffffu, x, o);
            if (lane >= o) x += y;
        }
        if (lane == 31) wsum[wid] = x;
        __syncthreads();
        if (wid == 0) {
            int w = wsum[lane];
            int xx = w;
            #pragma unroll
            for (int o = 1; o < 32; o <<= 1) {
                int y = __shfl_up_sync(0xffffffffu, xx, o);
                if (lane >= o) xx += y;
            }
            wsum[lane] = xx - w;
        }
        __syncthreads();
        int incl = x + wsum[wid];
        int excl = incl - v + off;
        if (i < NN) { g_rowptr[i] = excl; g_cursor[i] = excl; }
        __syncthreads();
        if (tid == 1023) off += incl;
        __syncthreads();
    }
    if (threadIdx.x == 0) g_rowptr[NN] = off;
}

__global__ void scatter_kernel(const int* __restrict__ src, const int* __restrict__ dst) {
    int i = blockIdx.x * blockDim.x + threadIdx.x;
    if (i >= ET) return;
    int s, t;
    if (i < EE) { s = src[i]; t = dst[i]; }
    else        { s = i - EE; t = s; }           // self loops
    int pos = atomicAdd(&g_cursor[t], 1);
    g_col[pos] = s;
}

// ---------------- expmap0 ----------------------------------------------------
__global__ void expmap_kernel(const float* __restrict__ x) {
    int gid = blockIdx.x * blockDim.x + threadIdx.x;
    int row = gid >> 5, lane = gid & 31;
    if (row >= NN) return;
    float4 v = ((const float4*)x)[row * 32 + lane];
    float ss = v.x * v.x + v.y * v.y + v.z * v.z + v.w * v.w;
    #pragma unroll
    for (int o = 16; o; o >>= 1) ss += __shfl_xor_sync(0xffffffffu, ss, o);
    float n = sqrtf(ss);
    n = fmaxf(n, 1e-15f);
    float sc = tanhf(n) / n;
    v.x *= sc; v.y *= sc; v.z *= sc; v.w *= sc;
    ((float4*)g_bufA)[row * 32 + lane] = v;
}

// ---------------- GEMM: H = A @ W, fused s/d epilogue (round-1 inner loop) ---
// block: 128 threads, tile 64 rows x 128 cols. W (64KB) + A tile (32KB) in smem.
__global__ void gemm_kernel(const float* __restrict__ A, const float* __restrict__ W,
                            const float* __restrict__ avs, const float* __restrict__ avd) {
    extern __shared__ float sm[];
    float* Ws = sm;              // [128][128]
    float* As = sm + 128 * 128;  // [64][128]
    int tid = threadIdx.x;
    int row0 = blockIdx.x * 64;

    for (int i = tid; i < (128 * 128) / 4; i += 128)
        ((float4*)Ws)[i] = ((const float4*)W)[i];
    for (int i = tid; i < (64 * 128) / 4; i += 128) {
        int r = i >> 5, c4 = i & 31;
        int row = row0 + r;
        float4 v = (row < NN) ? ((const float4*)A)[row * 32 + c4]
                              : make_float4(0.f, 0.f, 0.f, 0.f);
        ((float4*)As)[i] = v;
    }
    __syncthreads();

    int w = tid >> 5, lane = tid & 31;
    int r0 = w * 16;        // 16 rows per warp (all lanes share rows -> smem broadcast)
    int c0 = lane * 4;      // 4 cols per lane

    float acc[16][4];
    #pragma unroll
    for (int i = 0; i < 16; i++)
        #pragma unroll
        for (int j = 0; j < 4; j++) acc[i][j] = 0.f;

    #pragma unroll 4
    for (int k = 0; k < 128; k++) {
        float4 wk = *(const float4*)&Ws[k * 128 + c0];
        #pragma unroll
        for (int i = 0; i < 16; i++) {
            float a = As[(r0 + i) * 128 + k];
            acc[i][0] = fmaf(a, wk.x, acc[i][0]);
            acc[i][1] = fmaf(a, wk.y, acc[i][1]);
            acc[i][2] = fmaf(a, wk.z, acc[i][2]);
            acc[i][3] = fmaf(a, wk.w, acc[i][3]);
        }
    }

    float4 asv = *(const float4*)&avs[c0];
    float4 adv = *(const float4*)&avd[c0];
    #pragma unroll
    for (int i = 0; i < 16; i++) {
        int row = row0 + r0 + i;
        if (row < NN) {   // uniform across warp
            float4 o;
            o.x = acc[i][0]; o.y = acc[i][1]; o.z = acc[i][2]; o.w = acc[i][3];
            // store H as fp16 (halves the aggregation gather traffic)
            __half2 h0 = __floats2half2_rn(o.x, o.y);
            __half2 h1 = __floats2half2_rn(o.z, o.w);
            uint2 st;
            st.x = *(unsigned int*)&h0;
            st.y = *(unsigned int*)&h1;
            ((uint2*)g_bufH)[row * 32 + lane] = st;
            // s/d from full-precision accumulators
            float ps = o.x * asv.x + o.y * asv.y + o.z * asv.z + o.w * asv.w;
            float pd = o.x * adv.x + o.y * adv.y + o.z * adv.z + o.w * adv.w;
            #pragma unroll
            for (int off = 16; off; off >>= 1) {
                ps += __shfl_xor_sync(0xffffffffu, ps, off);
                pd += __shfl_xor_sync(0xffffffffu, pd, off);
            }
            if (lane == 0) { g_s[row] = ps; g_d[row] = pd; }
        }
    }
}

// ---------------- per-node attention aggregation (1 warp / node) -------------
__global__ void agg_kernel(const __half* __restrict__ H, const float* __restrict__ sarr,
                           const float* __restrict__ darr, const float* __restrict__ bias,
                           float* __restrict__ out, int act) {
    __shared__ float ebuf[8][128];
    int lane = threadIdx.x & 31, ws = threadIdx.x >> 5;
    int node = (blockIdx.x * blockDim.x + threadIdx.x) >> 5;
    if (node >= NN) return;

    int beg = g_rowptr[node], end = g_rowptr[node + 1];
    float di = darr[node];

    // pass 1: online softmax (per lane, then warp combine)
    float m = -1e30f, den = 0.f;
    for (int j = beg + lane; j < end; j += 32) {
        float e = sarr[g_col[j]] + di;
        e = e > 0.f ? e : 0.2f * e;
        float nm = fmaxf(m, e);
        den = den * __expf(m - nm) + __expf(e - nm);
        m = nm;
    }
    #pragma unroll
    for (int o = 16; o; o >>= 1) {
        float m2 = __shfl_xor_sync(0xffffffffu, m, o);
        float d2 = __shfl_xor_sync(0xffffffffu, den, o);
        float nm = fmaxf(m, m2);
        den = den * __expf(m - nm) + d2 * __expf(m2 - nm);
        m = nm;
    }
    float inv = 1.f / den;

    // pass 2: weighted gather-accumulate (alpha staged in smem per warp)
    float4 acc = make_float4(0.f, 0.f, 0.f, 0.f);
    for (int cb = beg; cb < end; cb += 128) {
        int cn = min(128, end - cb);
        for (int j = lane; j < cn; j += 32) {
            float e = sarr[g_col[cb + j]] + di;
            e = e > 0.f ? e : 0.2f * e;
            ebuf[ws][j] = __expf(e - m) * inv;
        }
        __syncwarp();
        for (int j = 0; j < cn; j++) {
            int sn = g_col[cb + j];              // broadcast load
            float al = ebuf[ws][j];
            uint2 hv = ((const uint2*)H)[sn * 32 + lane];   // fp16 row gather (8B/lane)
            __half2 p0 = *(__half2*)&hv.x;
            __half2 p1 = *(__half2*)&hv.y;
            float2 f0 = __half22float2(p0);
            float2 f1 = __half22float2(p1);
            acc.x = fmaf(al, f0.x, acc.x);
            acc.y = fmaf(al, f0.y, acc.y);
            acc.z = fmaf(al, f1.x, acc.z);
            acc.w = fmaf(al, f1.y, acc.w);
        }
        __syncwarp();
    }

    float4 bv = ((const float4*)bias)[lane];
    acc.x += bv.x; acc.y += bv.y; acc.z += bv.z; acc.w += bv.w;
    if (act) {
        acc.x = 2.f * tanhf(acc.x);
        acc.y = 2.f * tanhf(acc.y);
        acc.z = 2.f * tanhf(acc.z);
        acc.w = 2.f * tanhf(acc.w);
    }
    ((float4*)out)[node * 32 + lane] = acc;
}

// ---------------- launch ------------------------------------------------------
extern "C" void kernel_launch(void* const* d_in, const int* in_sizes, int n_in,
                              void* d_out, int out_size) {
    const float* x   = (const float*)d_in[0];
    const int*   ei  = (const int*)d_in[1];
    const int*   esrc = ei;
    const int*   edst = ei + EE;
    const float* W1  = (const float*)d_in[2];
    const float* a1s = (const float*)d_in[3];
    const float* a1d = (const float*)d_in[4];
    const float* b1  = (const float*)d_in[5];
    const float* W2  = (const float*)d_in[6];
    const float* a2s = (const float*)d_in[7];
    const float* a2d = (const float*)d_in[8];
    const float* b2  = (const float*)d_in[9];
    const float* W3  = (const float*)d_in[10];
    const float* a3s = (const float*)d_in[11];
    const float* a3d = (const float*)d_in[12];
    const float* b3  = (const float*)d_in[13];
    float* out = (float*)d_out;

    float *pA, *pS, *pD;
    __half *pH;
    cudaGetSymbolAddress((void**)&pA, g_bufA);
    cudaGetSymbolAddress((void**)&pH, g_bufH);
    cudaGetSymbolAddress((void**)&pS, g_s);
    cudaGetSymbolAddress((void**)&pD, g_d);

    const int SMEM = (128 * 128 + 64 * 128) * 4;   // 98304 B
    cudaFuncSetAttribute(gemm_kernel, cudaFuncAttributeMaxDynamicSharedMemorySize, SMEM);

    // CSR build (once per launch)
    init_count_kernel<<<(NN + 255) / 256, 256>>>();
    hist_kernel<<<(EE + 255) / 256, 256>>>(edst);
    scan_kernel<<<1, 1024>>>();
    scatter_kernel<<<(ET + 255) / 256, 256>>>(esrc, edst);

    // expmap0
    expmap_kernel<<<(NN * 32 + 255) / 256, 256>>>(x);

    int gemm_blocks = (NN + 63) / 64;
    int agg_blocks  = (NN + 7) / 8;

    // layer 1
    gemm_kernel<<<gemm_blocks, 128, SMEM>>>(pA, W1, a1s, a1d);
    agg_kernel<<<agg_blocks, 256>>>(pH, pS, pD, b1, pA, 1);
    // layer 2
    gemm_kernel<<<gemm_blocks, 128, SMEM>>>(pA, W2, a2s, a2d);
    agg_kernel<<<agg_blocks, 256>>>(pH, pS, pD, b2, pA, 1);
    // layer 3
    gemm_kernel<<<gemm_blocks, 128, SMEM>>>(pA, W3, a3s, a3d);
    agg_kernel<<<agg_blocks, 256>>>(pH, pS, pD, b3, out, 0);
}

// round 5
// speedup vs baseline: 1.5054x; 1.2628x over previous
#include <cuda_runtime.h>
#include <cuda_fp16.h>
#include <math.h>

#define NN 50000
#define EE 1600000
#define DD 128
#define ET (EE + NN)

// ---------------- scratch (static device globals; no allocation) ------------
__device__ __half g_bufA[NN * DD];   // layer input activations (fp16)
__device__ __half g_bufH[NN * DD];   // h = A @ W (fp16 for the gather)
__device__ float  g_s[NN];           // h . a_src
__device__ float  g_d[NN];           // h . a_dst
__device__ int    g_count[NN];
__device__ int    g_rowptr[NN + 1];
__device__ int    g_cursor[NN];
__device__ int    g_col[ET];         // CSR (by dst) source indices

// ---------------- CSR build --------------------------------------------------
__global__ void init_count_kernel() {
    int i = blockIdx.x * blockDim.x + threadIdx.x;
    if (i < NN) g_count[i] = 1;   // self loop
}

__global__ void hist_kernel(const int* __restrict__ dst) {
    int i = blockIdx.x * blockDim.x + threadIdx.x;
    if (i < EE) atomicAdd(&g_count[dst[i]], 1);
}

__global__ void scan_kernel() {
    __shared__ int wsum[32];
    __shared__ int off;
    int tid = threadIdx.x, lane = tid & 31, wid = tid >> 5;
    if (tid == 0) off = 0;
    __syncthreads();
    for (int base = 0; base < NN; base += 1024) {
        int i = base + tid;
        int v = (i < NN) ? g_count[i] : 0;
        int x = v;
        #pragma unroll
        for (int o = 1; o < 32; o <<= 1) {
            int y = __shfl_up_sync(0xffffffffu, x, o);
            if (lane >= o) x += y;
        }
        if (lane == 31) wsum[wid] = x;
        __syncthreads();
        if (wid == 0) {
            int w = wsum[lane];
            int xx = w;
            #pragma unroll
            for (int o = 1; o < 32; o <<= 1) {
                int y = __shfl_up_sync(0xffffffffu, xx, o);
                if (lane >= o) xx += y;
            }
            wsum[lane] = xx - w;
        }
        __syncthreads();
        int incl = x + wsum[wid];
        int excl = incl - v + off;
        if (i < NN) { g_rowptr[i] = excl; g_cursor[i] = excl; }
        __syncthreads();
        if (tid == 1023) off += incl;
        __syncthreads();
    }
    if (threadIdx.x == 0) g_rowptr[NN] = off;
}

__global__ void scatter_kernel(const int* __restrict__ src, const int* __restrict__ dst) {
    int i = blockIdx.x * blockDim.x + threadIdx.x;
    if (i >= ET) return;
    int s, t;
    if (i < EE) { s = src[i]; t = dst[i]; }
    else        { s = i - EE; t = s; }
    int pos = atomicAdd(&g_cursor[t], 1);
    g_col[pos] = s;
}

// ---------------- expmap0 (writes fp16 activations) ---------------------------
__global__ void expmap_kernel(const float* __restrict__ x) {
    int gid = blockIdx.x * blockDim.x + threadIdx.x;
    int row = gid >> 5, lane = gid & 31;
    if (row >= NN) return;
    float4 v = ((const float4*)x)[row * 32 + lane];
    float ss = v.x * v.x + v.y * v.y + v.z * v.z + v.w * v.w;
    #pragma unroll
    for (int o = 16; o; o >>= 1) ss += __shfl_xor_sync(0xffffffffu, ss, o);
    float n = sqrtf(ss);
    n = fmaxf(n, 1e-15f);
    float sc = tanhf(n) / n;
    __half2 h0 = __floats2half2_rn(v.x * sc, v.y * sc);
    __half2 h1 = __floats2half2_rn(v.z * sc, v.w * sc);
    uint2 st;
    st.x = *(unsigned int*)&h0;
    st.y = *(unsigned int*)&h1;
    ((uint2*)g_bufA)[row * 32 + lane] = st;
}

// ---------------- tensor-core GEMM: H = A @ W + fused s/d epilogue -----------
// mma.sync m16n8k16 fp16->fp32. Block: 128 threads (4 warps), tile 64x128.
// Wt in smem transposed [n][k] (stride 132 halves), As [row][k] (stride 132).
#define KS 132   // padded k-stride in halves

__device__ __forceinline__ void mma16816(float* c, unsigned a0, unsigned a1,
                                         unsigned a2, unsigned a3,
                                         unsigned b0, unsigned b1) {
    asm volatile(
        "mma.sync.aligned.m16n8k16.row.col.f32.f16.f16.f32 "
        "{%0,%1,%2,%3}, {%4,%5,%6,%7}, {%8,%9}, {%0,%1,%2,%3};"
        : "+f"(c[0]), "+f"(c[1]), "+f"(c[2]), "+f"(c[3])
        : "r"(a0), "r"(a1), "r"(a2), "r"(a3), "r"(b0), "r"(b1));
}

__global__ void gemm_kernel(const __half* __restrict__ A, const float* __restrict__ W,
                            const float* __restrict__ avs, const float* __restrict__ avd) {
    extern __shared__ char smraw[];
    __half* Wt  = (__half*)smraw;                    // [128][KS]
    __half* As  = Wt + 128 * KS;                     // [64][KS]
    float*  ass = (float*)(As + 64 * KS);            // [128]
    float*  ads = ass + 128;                         // [128]
    int tid = threadIdx.x;
    int row0 = blockIdx.x * 64;

    // stage W transposed -> Wt[n][k] fp16
    for (int i = tid; i < 128 * 128; i += 128) {
        int k = i >> 7, n = i & 127;
        Wt[n * KS + k] = __float2half(W[i]);
    }
    // stage A tile fp16 (already fp16 in gmem)
    for (int i = tid; i < 64 * 32; i += 128) {
        int r = i >> 5, c4 = i & 31;
        int row = row0 + r;
        uint2 v = (row < NN) ? ((const uint2*)A)[row * 32 + c4]
                             : make_uint2(0u, 0u);
        *(uint2*)&As[r * KS + c4 * 4] = v;
    }
    if (tid < 128) { ass[tid] = avs[tid]; ads[tid] = avd[tid]; }
    __syncthreads();

    int w = tid >> 5, lane = tid & 31;
    int gid = lane >> 2, tig = lane & 3;
    int rA = w * 16 + gid;          // warp-local row for c0/c1
    int rB = rA + 8;                // row for c2/c3

    float c[16][4];
    #pragma unroll
    for (int nt = 0; nt < 16; nt++)
        #pragma unroll
        for (int j = 0; j < 4; j++) c[nt][j] = 0.f;

    #pragma unroll
    for (int ks = 0; ks < 8; ks++) {
        int k0 = ks * 16;
        unsigned a0 = *(const unsigned*)&As[rA * KS + k0 + 2 * tig];
        unsigned a1 = *(const unsigned*)&As[rB * KS + k0 + 2 * tig];
        unsigned a2 = *(const unsigned*)&As[rA * KS + k0 + 2 * tig + 8];
        unsigned a3 = *(const unsigned*)&As[rB * KS + k0 + 2 * tig + 8];
        #pragma unroll
        for (int nt = 0; nt < 16; nt++) {
            const __half* bp = &Wt[(nt * 8 + gid) * KS + k0 + 2 * tig];
            unsigned b0 = *(const unsigned*)bp;
            unsigned b1 = *(const unsigned*)(bp + 8);
            mma16816(c[nt], a0, a1, a2, a3, b0, b1);
        }
    }

    // epilogue: store H (fp16) + s/d dot products from fp32 frags
    int rowA = row0 + rA, rowB = row0 + rB;
    float s0 = 0.f, s1 = 0.f, d0 = 0.f, d1 = 0.f;
    #pragma unroll
    for (int nt = 0; nt < 16; nt++) {
        int col = nt * 8 + 2 * tig;
        float2 as2 = *(const float2*)&ass[col];
        float2 ad2 = *(const float2*)&ads[col];
        s0 += c[nt][0] * as2.x + c[nt][1] * as2.y;
        d0 += c[nt][0] * ad2.x + c[nt][1] * ad2.y;
        s1 += c[nt][2] * as2.x + c[nt][3] * as2.y;
        d1 += c[nt][2] * ad2.x + c[nt][3] * ad2.y;
        if (rowA < NN) {
            __half2 h = __floats2half2_rn(c[nt][0], c[nt][1]);
            *(unsigned*)&g_bufH[rowA * 128 + col] = *(unsigned*)&h;
        }
        if (rowB < NN) {
            __half2 h = __floats2half2_rn(c[nt][2], c[nt][3]);
            *(unsigned*)&g_bufH[rowB * 128 + col] = *(unsigned*)&h;
        }
    }
    // reduce over the 4 lanes of the quad (tig dimension)
    #pragma unroll
    for (int o = 1; o <= 2; o <<= 1) {
        s0 += __shfl_xor_sync(0xffffffffu, s0, o);
        d0 += __shfl_xor_sync(0xffffffffu, d0, o);
        s1 += __shfl_xor_sync(0xffffffffu, s1, o);
        d1 += __shfl_xor_sync(0xffffffffu, d1, o);
    }
    if (tig == 0) {
        if (rowA < NN) { g_s[rowA] = s0; g_d[rowA] = d0; }
        if (rowB < NN) { g_s[rowB] = s1; g_d[rowB] = d1; }
    }
}

// ---------------- per-node attention aggregation (1 warp / node) -------------
__global__ void agg_kernel(const __half* __restrict__ H, const float* __restrict__ sarr,
                           const float* __restrict__ darr, const float* __restrict__ bias,
                           float* __restrict__ outF, __half* __restrict__ outH, int act) {
    __shared__ float ebuf[8][128];
    int lane = threadIdx.x & 31, ws = threadIdx.x >> 5;
    int node = (blockIdx.x * blockDim.x + threadIdx.x) >> 5;
    if (node >= NN) return;

    int beg = g_rowptr[node], end = g_rowptr[node + 1];
    float di = darr[node];

    // pass 1: online softmax
    float m = -1e30f, den = 0.f;
    for (int j = beg + lane; j < end; j += 32) {
        float e = sarr[g_col[j]] + di;
        e = e > 0.f ? e : 0.2f * e;
        float nm = fmaxf(m, e);
        den = den * __expf(m - nm) + __expf(e - nm);
        m = nm;
    }
    #pragma unroll
    for (int o = 16; o; o >>= 1) {
        float m2 = __shfl_xor_sync(0xffffffffu, m, o);
        float d2 = __shfl_xor_sync(0xffffffffu, den, o);
        float nm = fmaxf(m, m2);
        den = den * __expf(m - nm) + d2 * __expf(m2 - nm);
        m = nm;
    }
    float inv = 1.f / den;

    // pass 2: weighted gather-accumulate
    float4 acc = make_float4(0.f, 0.f, 0.f, 0.f);
    for (int cb = beg; cb < end; cb += 128) {
        int cn = min(128, end - cb);
        for (int j = lane; j < cn; j += 32) {
            float e = sarr[g_col[cb + j]] + di;
            e = e > 0.f ? e : 0.2f * e;
            ebuf[ws][j] = __expf(e - m) * inv;
        }
        __syncwarp();
        for (int j = 0; j < cn; j++) {
            int sn = g_col[cb + j];
            float al = ebuf[ws][j];
            uint2 hv = ((const uint2*)H)[sn * 32 + lane];
            __half2 p0 = *(__half2*)&hv.x;
            __half2 p1 = *(__half2*)&hv.y;
            float2 f0 = __half22float2(p0);
            float2 f1 = __half22float2(p1);
            acc.x = fmaf(al, f0.x, acc.x);
            acc.y = fmaf(al, f0.y, acc.y);
            acc.z = fmaf(al, f1.x, acc.z);
            acc.w = fmaf(al, f1.y, acc.w);
        }
        __syncwarp();
    }

    float4 bv = ((const float4*)bias)[lane];
    acc.x += bv.x; acc.y += bv.y; acc.z += bv.z; acc.w += bv.w;
    if (act) {
        acc.x = 2.f * tanhf(acc.x);
        acc.y = 2.f * tanhf(acc.y);
        acc.z = 2.f * tanhf(acc.z);
        acc.w = 2.f * tanhf(acc.w);
        __half2 h0 = __floats2half2_rn(acc.x, acc.y);
        __half2 h1 = __floats2half2_rn(acc.z, acc.w);
        uint2 st;
        st.x = *(unsigned int*)&h0;
        st.y = *(unsigned int*)&h1;
        ((uint2*)outH)[node * 32 + lane] = st;
    } else {
        ((float4*)outF)[node * 32 + lane] = acc;
    }
}

// ---------------- launch ------------------------------------------------------
extern "C" void kernel_launch(void* const* d_in, const int* in_sizes, int n_in,
                              void* d_out, int out_size) {
    const float* x   = (const float*)d_in[0];
    const int*   ei  = (const int*)d_in[1];
    const int*   esrc = ei;
    const int*   edst = ei + EE;
    const float* W1  = (const float*)d_in[2];
    const float* a1s = (const float*)d_in[3];
    const float* a1d = (const float*)d_in[4];
    const float* b1  = (const float*)d_in[5];
    const float* W2  = (const float*)d_in[6];
    const float* a2s = (const float*)d_in[7];
    const float* a2d = (const float*)d_in[8];
    const float* b2  = (const float*)d_in[9];
    const float* W3  = (const float*)d_in[10];
    const float* a3s = (const float*)d_in[11];
    const float* a3d = (const float*)d_in[12];
    const float* b3  = (const float*)d_in[13];
    float* out = (float*)d_out;

    float *pS, *pD;
    __half *pA, *pH;
    cudaGetSymbolAddress((void**)&pA, g_bufA);
    cudaGetSymbolAddress((void**)&pH, g_bufH);
    cudaGetSymbolAddress((void**)&pS, g_s);
    cudaGetSymbolAddress((void**)&pD, g_d);

    const int SMEM = (128 * KS + 64 * KS) * 2 + 2 * 128 * 4;   // ~51.7 KB
    cudaFuncSetAttribute(gemm_kernel, cudaFuncAttributeMaxDynamicSharedMemorySize, SMEM);

    // CSR build (once per launch)
    init_count_kernel<<<(NN + 255) / 256, 256>>>();
    hist_kernel<<<(EE + 255) / 256, 256>>>(edst);
    scan_kernel<<<1, 1024>>>();
    scatter_kernel<<<(ET + 255) / 256, 256>>>(esrc, edst);

    // expmap0
    expmap_kernel<<<(NN * 32 + 255) / 256, 256>>>(x);

    int gemm_blocks = (NN + 63) / 64;
    int agg_blocks  = (NN + 7) / 8;

    // layer 1
    gemm_kernel<<<gemm_blocks, 128, SMEM>>>(pA, W1, a1s, a1d);
    agg_kernel<<<agg_blocks, 256>>>(pH, pS, pD, b1, nullptr, pA, 1);
    // layer 2
    gemm_kernel<<<gemm_blocks, 128, SMEM>>>(pA, W2, a2s, a2d);
    agg_kernel<<<agg_blocks, 256>>>(pH, pS, pD, b2, nullptr, pA, 1);
    // layer 3
    gemm_kernel<<<gemm_blocks, 128, SMEM>>>(pA, W3, a3s, a3d);
    agg_kernel<<<agg_blocks, 256>>>(pH, pS, pD, b3, out, nullptr, 0);
}

// round 6
// speedup vs baseline: 1.5521x; 1.0310x over previous
#include <cuda_runtime.h>
#include <cuda_fp16.h>
#include <math.h>

#define NN 50000
#define EE 1600000
#define DD 128
#define ET (EE + NN)

// ---------------- scratch (static device globals; no allocation) ------------
__device__ __half g_bufA[NN * DD];   // layer input activations (fp16)
__device__ __half g_bufH[NN * DD];   // h = A @ W (fp16 for the gather)
__device__ float  g_s[NN];           // h . a_src
__device__ float  g_d[NN];           // h . a_dst
__device__ int    g_count[NN];
__device__ int    g_rowptr[NN + 1];
__device__ int    g_cursor[NN];
__device__ int    g_col[ET];         // CSR (by dst) source indices

// ---------------- CSR build --------------------------------------------------
__global__ void init_count_kernel() {
    int i = blockIdx.x * blockDim.x + threadIdx.x;
    if (i < NN) g_count[i] = 1;   // self loop
}

__global__ void hist_kernel(const int* __restrict__ dst) {
    int i = blockIdx.x * blockDim.x + threadIdx.x;
    if (i < EE) atomicAdd(&g_count[dst[i]], 1);
}

__global__ void scan_kernel() {
    __shared__ int wsum[32];
    __shared__ int off;
    int tid = threadIdx.x, lane = tid & 31, wid = tid >> 5;
    if (tid == 0) off = 0;
    __syncthreads();
    for (int base = 0; base < NN; base += 1024) {
        int i = base + tid;
        int v = (i < NN) ? g_count[i] : 0;
        int x = v;
        #pragma unroll
        for (int o = 1; o < 32; o <<= 1) {
            int y = __shfl_up_sync(0xffffffffu, x, o);
            if (lane >= o) x += y;
        }
        if (lane == 31) wsum[wid] = x;
        __syncthreads();
        if (wid == 0) {
            int w = wsum[lane];
            int xx = w;
            #pragma unroll
            for (int o = 1; o < 32; o <<= 1) {
                int y = __shfl_up_sync(0xffffffffu, xx, o);
                if (lane >= o) xx += y;
            }
            wsum[lane] = xx - w;
        }
        __syncthreads();
        int incl = x + wsum[wid];
        int excl = incl - v + off;
        if (i < NN) { g_rowptr[i] = excl; g_cursor[i] = excl; }
        __syncthreads();
        if (tid == 1023) off += incl;
        __syncthreads();
    }
    if (threadIdx.x == 0) g_rowptr[NN] = off;
}

__global__ void scatter_kernel(const int* __restrict__ src, const int* __restrict__ dst) {
    int i = blockIdx.x * blockDim.x + threadIdx.x;
    if (i >= ET) return;
    int s, t;
    if (i < EE) { s = src[i]; t = dst[i]; }
    else        { s = i - EE; t = s; }
    int pos = atomicAdd(&g_cursor[t], 1);
    g_col[pos] = s;
}

// ---------------- expmap0 (writes fp16 activations) ---------------------------
__global__ void expmap_kernel(const float* __restrict__ x) {
    int gid = blockIdx.x * blockDim.x + threadIdx.x;
    int row = gid >> 5, lane = gid & 31;
    if (row >= NN) return;
    float4 v = ((const float4*)x)[row * 32 + lane];
    float ss = v.x * v.x + v.y * v.y + v.z * v.z + v.w * v.w;
    #pragma unroll
    for (int o = 16; o; o >>= 1) ss += __shfl_xor_sync(0xffffffffu, ss, o);
    float n = sqrtf(ss);
    n = fmaxf(n, 1e-15f);
    float sc = tanhf(n) / n;
    __half2 h0 = __floats2half2_rn(v.x * sc, v.y * sc);
    __half2 h1 = __floats2half2_rn(v.z * sc, v.w * sc);
    uint2 st;
    st.x = *(unsigned int*)&h0;
    st.y = *(unsigned int*)&h1;
    ((uint2*)g_bufA)[row * 32 + lane] = st;
}

// ---------------- tensor-core GEMM: H = A @ W + fused s/d epilogue -----------
#define KS 132   // padded k-stride in halves

__device__ __forceinline__ void mma16816(float* c, unsigned a0, unsigned a1,
                                         unsigned a2, unsigned a3,
                                         unsigned b0, unsigned b1) {
    asm volatile(
        "mma.sync.aligned.m16n8k16.row.col.f32.f16.f16.f32 "
        "{%0,%1,%2,%3}, {%4,%5,%6,%7}, {%8,%9}, {%0,%1,%2,%3};"
        : "+f"(c[0]), "+f"(c[1]), "+f"(c[2]), "+f"(c[3])
        : "r"(a0), "r"(a1), "r"(a2), "r"(a3), "r"(b0), "r"(b1));
}

__global__ void gemm_kernel(const __half* __restrict__ A, const float* __restrict__ W,
                            const float* __restrict__ avs, const float* __restrict__ avd) {
    extern __shared__ char smraw[];
    __half* Wt  = (__half*)smraw;                    // [128][KS]
    __half* As  = Wt + 128 * KS;                     // [64][KS]
    float*  ass = (float*)(As + 64 * KS);            // [128]
    float*  ads = ass + 128;                         // [128]
    int tid = threadIdx.x;
    int row0 = blockIdx.x * 64;

    for (int i = tid; i < 128 * 128; i += 128) {
        int k = i >> 7, n = i & 127;
        Wt[n * KS + k] = __float2half(W[i]);
    }
    for (int i = tid; i < 64 * 32; i += 128) {
        int r = i >> 5, c4 = i & 31;
        int row = row0 + r;
        uint2 v = (row < NN) ? ((const uint2*)A)[row * 32 + c4]
                             : make_uint2(0u, 0u);
        *(uint2*)&As[r * KS + c4 * 4] = v;
    }
    if (tid < 128) { ass[tid] = avs[tid]; ads[tid] = avd[tid]; }
    __syncthreads();

    int w = tid >> 5, lane = tid & 31;
    int gid = lane >> 2, tig = lane & 3;
    int rA = w * 16 + gid;
    int rB = rA + 8;

    float c[16][4];
    #pragma unroll
    for (int nt = 0; nt < 16; nt++)
        #pragma unroll
        for (int j = 0; j < 4; j++) c[nt][j] = 0.f;

    #pragma unroll
    for (int ks = 0; ks < 8; ks++) {
        int k0 = ks * 16;
        unsigned a0 = *(const unsigned*)&As[rA * KS + k0 + 2 * tig];
        unsigned a1 = *(const unsigned*)&As[rB * KS + k0 + 2 * tig];
        unsigned a2 = *(const unsigned*)&As[rA * KS + k0 + 2 * tig + 8];
        unsigned a3 = *(const unsigned*)&As[rB * KS + k0 + 2 * tig + 8];
        #pragma unroll
        for (int nt = 0; nt < 16; nt++) {
            const __half* bp = &Wt[(nt * 8 + gid) * KS + k0 + 2 * tig];
            unsigned b0 = *(const unsigned*)bp;
            unsigned b1 = *(const unsigned*)(bp + 8);
            mma16816(c[nt], a0, a1, a2, a3, b0, b1);
        }
    }

    int rowA = row0 + rA, rowB = row0 + rB;
    float s0 = 0.f, s1 = 0.f, d0 = 0.f, d1 = 0.f;
    #pragma unroll
    for (int nt = 0; nt < 16; nt++) {
        int col = nt * 8 + 2 * tig;
        float2 as2 = *(const float2*)&ass[col];
        float2 ad2 = *(const float2*)&ads[col];
        s0 += c[nt][0] * as2.x + c[nt][1] * as2.y;
        d0 += c[nt][0] * ad2.x + c[nt][1] * ad2.y;
        s1 += c[nt][2] * as2.x + c[nt][3] * as2.y;
        d1 += c[nt][2] * ad2.x + c[nt][3] * ad2.y;
        if (rowA < NN) {
            __half2 h = __floats2half2_rn(c[nt][0], c[nt][1]);
            *(unsigned*)&g_bufH[rowA * 128 + col] = *(unsigned*)&h;
        }
        if (rowB < NN) {
            __half2 h = __floats2half2_rn(c[nt][2], c[nt][3]);
            *(unsigned*)&g_bufH[rowB * 128 + col] = *(unsigned*)&h;
        }
    }
    #pragma unroll
    for (int o = 1; o <= 2; o <<= 1) {
        s0 += __shfl_xor_sync(0xffffffffu, s0, o);
        d0 += __shfl_xor_sync(0xffffffffu, d0, o);
        s1 += __shfl_xor_sync(0xffffffffu, s1, o);
        d1 += __shfl_xor_sync(0xffffffffu, d1, o);
    }
    if (tig == 0) {
        if (rowA < NN) { g_s[rowA] = s0; g_d[rowA] = d0; }
        if (rowB < NN) { g_s[rowB] = s1; g_d[rowB] = d1; }
    }
}

// ---------------- aggregation helpers -----------------------------------------
// unrolled gather-accumulate over cn staged edges (sn in sb, alpha in eb)
__device__ __forceinline__ void gather_acc(const __half* __restrict__ H,
                                           const int* sb, const float* eb,
                                           int cn, int lane, float4& acc) {
    int j = 0;
    for (; j + 8 <= cn; j += 8) {
        uint2 hv[8];
        float al[8];
        #pragma unroll
        for (int u = 0; u < 8; u++) {
            int sn = sb[j + u];                       // smem broadcast
            al[u] = eb[j + u];
            hv[u] = ((const uint2*)H)[sn * 32 + lane]; // 8 gathers in flight
        }
        #pragma unroll
        for (int u = 0; u < 8; u++) {
            __half2 p0 = *(__half2*)&hv[u].x;
            __half2 p1 = *(__half2*)&hv[u].y;
            float2 f0 = __half22float2(p0);
            float2 f1 = __half22float2(p1);
            acc.x = fmaf(al[u], f0.x, acc.x);
            acc.y = fmaf(al[u], f0.y, acc.y);
            acc.z = fmaf(al[u], f1.x, acc.z);
            acc.w = fmaf(al[u], f1.y, acc.w);
        }
    }
    for (; j < cn; j++) {
        int sn = sb[j];
        float al = eb[j];
        uint2 hv = ((const uint2*)H)[sn * 32 + lane];
        __half2 p0 = *(__half2*)&hv.x;
        __half2 p1 = *(__half2*)&hv.y;
        float2 f0 = __half22float2(p0);
        float2 f1 = __half22float2(p1);
        acc.x = fmaf(al, f0.x, acc.x);
        acc.y = fmaf(al, f0.y, acc.y);
        acc.z = fmaf(al, f1.x, acc.z);
        acc.w = fmaf(al, f1.y, acc.w);
    }
}

// ---------------- per-node attention aggregation (1 warp / node) -------------
__global__ void agg_kernel(const __half* __restrict__ H, const float* __restrict__ sarr,
                           const float* __restrict__ darr, const float* __restrict__ bias,
                           float* __restrict__ outF, __half* __restrict__ outH, int act) {
    __shared__ float ebuf[8][128];
    __shared__ int   sbuf[8][128];
    int lane = threadIdx.x & 31, ws = threadIdx.x >> 5;
    int node = (blockIdx.x * blockDim.x + threadIdx.x) >> 5;
    if (node >= NN) return;

    int beg = g_rowptr[node], end = g_rowptr[node + 1];
    int deg = end - beg;
    float di = darr[node];
    float* eb = ebuf[ws];
    int*   sb = sbuf[ws];

    float m = -1e30f, den = 0.f;
    bool small = (deg <= 128);

    // pass 1: online softmax; stage sn + raw logit when the node fits in smem
    if (small) {
        for (int j = lane; j < deg; j += 32) {
            int sn = g_col[beg + j];
            float e = sarr[sn] + di;
            e = e > 0.f ? e : 0.2f * e;
            sb[j] = sn;
            eb[j] = e;
            float nm = fmaxf(m, e);
            den = den * __expf(m - nm) + __expf(e - nm);
            m = nm;
        }
    } else {
        for (int j = beg + lane; j < end; j += 32) {
            float e = sarr[g_col[j]] + di;
            e = e > 0.f ? e : 0.2f * e;
            float nm = fmaxf(m, e);
            den = den * __expf(m - nm) + __expf(e - nm);
            m = nm;
        }
    }
    #pragma unroll
    for (int o = 16; o; o >>= 1) {
        float m2 = __shfl_xor_sync(0xffffffffu, m, o);
        float d2 = __shfl_xor_sync(0xffffffffu, den, o);
        float nm = fmaxf(m, m2);
        den = den * __expf(m - nm) + d2 * __expf(m2 - nm);
        m = nm;
    }
    float inv = 1.f / den;

    // pass 2
    float4 acc = make_float4(0.f, 0.f, 0.f, 0.f);
    if (small) {
        for (int j = lane; j < deg; j += 32)
            eb[j] = __expf(eb[j] - m) * inv;      // logit -> alpha in place
        __syncwarp();
        gather_acc(H, sb, eb, deg, lane, acc);
        __syncwarp();
    } else {
        for (int cb = beg; cb < end; cb += 128) {
            int cn = min(128, end - cb);
            for (int j = lane; j < cn; j += 32) {
                int sn = g_col[cb + j];
                float e = sarr[sn] + di;
                e = e > 0.f ? e : 0.2f * e;
                sb[j] = sn;
                eb[j] = __expf(e - m) * inv;
            }
            __syncwarp();
            gather_acc(H, sb, eb, cn, lane, acc);
            __syncwarp();
        }
    }

    float4 bv = ((const float4*)bias)[lane];
    acc.x += bv.x; acc.y += bv.y; acc.z += bv.z; acc.w += bv.w;
    if (act) {
        acc.x = 2.f * tanhf(acc.x);
        acc.y = 2.f * tanhf(acc.y);
        acc.z = 2.f * tanhf(acc.z);
        acc.w = 2.f * tanhf(acc.w);
        __half2 h0 = __floats2half2_rn(acc.x, acc.y);
        __half2 h1 = __floats2half2_rn(acc.z, acc.w);
        uint2 st;
        st.x = *(unsigned int*)&h0;
        st.y = *(unsigned int*)&h1;
        ((uint2*)outH)[node * 32 + lane] = st;
    } else {
        ((float4*)outF)[node * 32 + lane] = acc;
    }
}

// ---------------- launch ------------------------------------------------------
extern "C" void kernel_launch(void* const* d_in, const int* in_sizes, int n_in,
                              void* d_out, int out_size) {
    const float* x   = (const float*)d_in[0];
    const int*   ei  = (const int*)d_in[1];
    const int*   esrc = ei;
    const int*   edst = ei + EE;
    const float* W1  = (const float*)d_in[2];
    const float* a1s = (const float*)d_in[3];
    const float* a1d = (const float*)d_in[4];
    const float* b1  = (const float*)d_in[5];
    const float* W2  = (const float*)d_in[6];
    const float* a2s = (const float*)d_in[7];
    const float* a2d = (const float*)d_in[8];
    const float* b2  = (const float*)d_in[9];
    const float* W3  = (const float*)d_in[10];
    const float* a3s = (const float*)d_in[11];
    const float* a3d = (const float*)d_in[12];
    const float* b3  = (const float*)d_in[13];
    float* out = (float*)d_out;

    float *pS, *pD;
    __half *pA, *pH;
    cudaGetSymbolAddress((void**)&pA, g_bufA);
    cudaGetSymbolAddress((void**)&pH, g_bufH);
    cudaGetSymbolAddress((void**)&pS, g_s);
    cudaGetSymbolAddress((void**)&pD, g_d);

    const int SMEM = (128 * KS + 64 * KS) * 2 + 2 * 128 * 4;   // ~51.7 KB
    cudaFuncSetAttribute(gemm_kernel, cudaFuncAttributeMaxDynamicSharedMemorySize, SMEM);

    // CSR build (once per launch)
    init_count_kernel<<<(NN + 255) / 256, 256>>>();
    hist_kernel<<<(EE + 255) / 256, 256>>>(edst);
    scan_kernel<<<1, 1024>>>();
    scatter_kernel<<<(ET + 255) / 256, 256>>>(esrc, edst);

    // expmap0
    expmap_kernel<<<(NN * 32 + 255) / 256, 256>>>(x);

    int gemm_blocks = (NN + 63) / 64;
    int agg_blocks  = (NN + 7) / 8;

    // layer 1
    gemm_kernel<<<gemm_blocks, 128, SMEM>>>(pA, W1, a1s, a1d);
    agg_kernel<<<agg_blocks, 256>>>(pH, pS, pD, b1, nullptr, pA, 1);
    // layer 2
    gemm_kernel<<<gemm_blocks, 128, SMEM>>>(pA, W2, a2s, a2d);
    agg_kernel<<<agg_blocks, 256>>>(pH, pS, pD, b2, nullptr, pA, 1);
    // layer 3
    gemm_kernel<<<gemm_blocks, 128, SMEM>>>(pA, W3, a3s, a3d);
    agg_kernel<<<agg_blocks, 256>>>(pH, pS, pD, b3, out, nullptr, 0);
}

// round 7
// speedup vs baseline: 1.5735x; 1.0138x over previous
#include <cuda_runtime.h>
#include <cuda_fp16.h>
#include <math.h>

#define NN 50000
#define EE 1600000
#define DD 128
#define ET (EE + NN)

// ---------------- scratch (static device globals; no allocation) ------------
__device__ __half g_bufA[NN * DD];   // layer input activations (fp16)
__device__ __half g_bufH[NN * DD];   // h = A @ W (fp16 for the gather)
__device__ float  g_s[NN];           // h . a_src
__device__ float  g_d[NN];           // h . a_dst
__device__ int    g_count[NN];
__device__ int    g_rowptr[NN + 1];
__device__ int    g_cursor[NN];
__device__ int    g_col[ET];         // CSR (by dst) source indices

// ---------------- CSR build --------------------------------------------------
__global__ void init_count_kernel() {
    int i = blockIdx.x * blockDim.x + threadIdx.x;
    if (i < NN) g_count[i] = 1;   // self loop
}

__global__ void hist_kernel(const int* __restrict__ dst) {
    int i = blockIdx.x * blockDim.x + threadIdx.x;
    if (i < EE) atomicAdd(&g_count[dst[i]], 1);
}

__global__ void scan_kernel() {
    __shared__ int wsum[32];
    __shared__ int off;
    int tid = threadIdx.x, lane = tid & 31, wid = tid >> 5;
    if (tid == 0) off = 0;
    __syncthreads();
    for (int base = 0; base < NN; base += 1024) {
        int i = base + tid;
        int v = (i < NN) ? g_count[i] : 0;
        int x = v;
        #pragma unroll
        for (int o = 1; o < 32; o <<= 1) {
            int y = __shfl_up_sync(0xffffffffu, x, o);
            if (lane >= o) x += y;
        }
        if (lane == 31) wsum[wid] = x;
        __syncthreads();
        if (wid == 0) {
            int w = wsum[lane];
            int xx = w;
            #pragma unroll
            for (int o = 1; o < 32; o <<= 1) {
                int y = __shfl_up_sync(0xffffffffu, xx, o);
                if (lane >= o) xx += y;
            }
            wsum[lane] = xx - w;
        }
        __syncthreads();
        int incl = x + wsum[wid];
        int excl = incl - v + off;
        if (i < NN) { g_rowptr[i] = excl; g_cursor[i] = excl; }
        __syncthreads();
        if (tid == 1023) off += incl;
        __syncthreads();
    }
    if (threadIdx.x == 0) g_rowptr[NN] = off;
}

__global__ void scatter_kernel(const int* __restrict__ src, const int* __restrict__ dst) {
    int i = blockIdx.x * blockDim.x + threadIdx.x;
    if (i >= ET) return;
    int s, t;
    if (i < EE) { s = src[i]; t = dst[i]; }
    else        { s = i - EE; t = s; }
    int pos = atomicAdd(&g_cursor[t], 1);
    g_col[pos] = s;
}

// ---------------- expmap0 (writes fp16 activations) ---------------------------
__global__ void expmap_kernel(const float* __restrict__ x) {
    int gid = blockIdx.x * blockDim.x + threadIdx.x;
    int row = gid >> 5, lane = gid & 31;
    if (row >= NN) return;
    float4 v = ((const float4*)x)[row * 32 + lane];
    float ss = v.x * v.x + v.y * v.y + v.z * v.z + v.w * v.w;
    #pragma unroll
    for (int o = 16; o; o >>= 1) ss += __shfl_xor_sync(0xffffffffu, ss, o);
    float n = sqrtf(ss);
    n = fmaxf(n, 1e-15f);
    float sc = tanhf(n) / n;
    __half2 h0 = __floats2half2_rn(v.x * sc, v.y * sc);
    __half2 h1 = __floats2half2_rn(v.z * sc, v.w * sc);
    uint2 st;
    st.x = *(unsigned int*)&h0;
    st.y = *(unsigned int*)&h1;
    ((uint2*)g_bufA)[row * 32 + lane] = st;
}

// ---------------- tensor-core GEMM: H = A @ W + fused s/d epilogue -----------
#define KS 132   // padded k-stride in halves

__device__ __forceinline__ void mma16816(float* c, unsigned a0, unsigned a1,
                                         unsigned a2, unsigned a3,
                                         unsigned b0, unsigned b1) {
    asm volatile(
        "mma.sync.aligned.m16n8k16.row.col.f32.f16.f16.f32 "
        "{%0,%1,%2,%3}, {%4,%5,%6,%7}, {%8,%9}, {%0,%1,%2,%3};"
        : "+f"(c[0]), "+f"(c[1]), "+f"(c[2]), "+f"(c[3])
        : "r"(a0), "r"(a1), "r"(a2), "r"(a3), "r"(b0), "r"(b1));
}

__global__ void gemm_kernel(const __half* __restrict__ A, const float* __restrict__ W,
                            const float* __restrict__ avs, const float* __restrict__ avd) {
    extern __shared__ char smraw[];
    __half* Wt  = (__half*)smraw;                    // [128][KS]
    __half* As  = Wt + 128 * KS;                     // [64][KS]
    float*  ass = (float*)(As + 64 * KS);            // [128]
    float*  ads = ass + 128;                         // [128]
    int tid = threadIdx.x;
    int row0 = blockIdx.x * 64;

    for (int i = tid; i < 128 * 128; i += 128) {
        int k = i >> 7, n = i & 127;
        Wt[n * KS + k] = __float2half(W[i]);
    }
    for (int i = tid; i < 64 * 32; i += 128) {
        int r = i >> 5, c4 = i & 31;
        int row = row0 + r;
        uint2 v = (row < NN) ? ((const uint2*)A)[row * 32 + c4]
                             : make_uint2(0u, 0u);
        *(uint2*)&As[r * KS + c4 * 4] = v;
    }
    if (tid < 128) { ass[tid] = avs[tid]; ads[tid] = avd[tid]; }
    __syncthreads();

    int w = tid >> 5, lane = tid & 31;
    int gid = lane >> 2, tig = lane & 3;
    int rA = w * 16 + gid;
    int rB = rA + 8;

    float c[16][4];
    #pragma unroll
    for (int nt = 0; nt < 16; nt++)
        #pragma unroll
        for (int j = 0; j < 4; j++) c[nt][j] = 0.f;

    #pragma unroll
    for (int ks = 0; ks < 8; ks++) {
        int k0 = ks * 16;
        unsigned a0 = *(const unsigned*)&As[rA * KS + k0 + 2 * tig];
        unsigned a1 = *(const unsigned*)&As[rB * KS + k0 + 2 * tig];
        unsigned a2 = *(const unsigned*)&As[rA * KS + k0 + 2 * tig + 8];
        unsigned a3 = *(const unsigned*)&As[rB * KS + k0 + 2 * tig + 8];
        #pragma unroll
        for (int nt = 0; nt < 16; nt++) {
            const __half* bp = &Wt[(nt * 8 + gid) * KS + k0 + 2 * tig];
            unsigned b0 = *(const unsigned*)bp;
            unsigned b1 = *(const unsigned*)(bp + 8);
            mma16816(c[nt], a0, a1, a2, a3, b0, b1);
        }
    }

    int rowA = row0 + rA, rowB = row0 + rB;
    float s0 = 0.f, s1 = 0.f, d0 = 0.f, d1 = 0.f;
    #pragma unroll
    for (int nt = 0; nt < 16; nt++) {
        int col = nt * 8 + 2 * tig;
        float2 as2 = *(const float2*)&ass[col];
        float2 ad2 = *(const float2*)&ads[col];
        s0 += c[nt][0] * as2.x + c[nt][1] * as2.y;
        d0 += c[nt][0] * ad2.x + c[nt][1] * ad2.y;
        s1 += c[nt][2] * as2.x + c[nt][3] * as2.y;
        d1 += c[nt][2] * ad2.x + c[nt][3] * ad2.y;
        if (rowA < NN) {
            __half2 h = __floats2half2_rn(c[nt][0], c[nt][1]);
            *(unsigned*)&g_bufH[rowA * 128 + col] = *(unsigned*)&h;
        }
        if (rowB < NN) {
            __half2 h = __floats2half2_rn(c[nt][2], c[nt][3]);
            *(unsigned*)&g_bufH[rowB * 128 + col] = *(unsigned*)&h;
        }
    }
    #pragma unroll
    for (int o = 1; o <= 2; o <<= 1) {
        s0 += __shfl_xor_sync(0xffffffffu, s0, o);
        d0 += __shfl_xor_sync(0xffffffffu, d0, o);
        s1 += __shfl_xor_sync(0xffffffffu, s1, o);
        d1 += __shfl_xor_sync(0xffffffffu, d1, o);
    }
    if (tig == 0) {
        if (rowA < NN) { g_s[rowA] = s0; g_d[rowA] = d0; }
        if (rowB < NN) { g_s[rowB] = s1; g_d[rowB] = d1; }
    }
}

// ---------------- aggregation helpers -----------------------------------------
// pair-gather: 2 edges per warp-iteration, LDG.128 (16B = 8 fp16 feats/lane),
// L1-bypass (__ldcg) so sarr stays L1-resident. cn must be EVEN (pad upstream).
__device__ __forceinline__ void gather_acc2(const __half* __restrict__ H,
                                            const int* sb, const float* eb,
                                            int cn, int half, int fl,
                                            float* acc8) {
    int j = 0;
    for (; j + 16 <= cn; j += 16) {      // 8 pairs = 16 edges
        uint4 hv[8];
        float al[8];
        #pragma unroll
        for (int u = 0; u < 8; u++) {
            int idx = j + 2 * u + half;
            int sn = sb[idx];
            al[u] = eb[idx];
            hv[u] = __ldcg(((const uint4*)(H + sn * 128)) + fl);
        }
        #pragma unroll
        for (int u = 0; u < 8; u++) {
            const __half2* p = (const __half2*)&hv[u];
            #pragma unroll
            for (int q = 0; q < 4; q++) {
                float2 f = __half22float2(p[q]);
                acc8[2 * q + 0] = fmaf(al[u], f.x, acc8[2 * q + 0]);
                acc8[2 * q + 1] = fmaf(al[u], f.y, acc8[2 * q + 1]);
            }
        }
    }
    for (; j < cn; j += 2) {             // leftover pairs
        int idx = j + half;
        int sn = sb[idx];
        float al = eb[idx];
        uint4 hv = __ldcg(((const uint4*)(H + sn * 128)) + fl);
        const __half2* p = (const __half2*)&hv;
        #pragma unroll
        for (int q = 0; q < 4; q++) {
            float2 f = __half22float2(p[q]);
            acc8[2 * q + 0] = fmaf(al, f.x, acc8[2 * q + 0]);
            acc8[2 * q + 1] = fmaf(al, f.y, acc8[2 * q + 1]);
        }
    }
}

// ---------------- per-node attention aggregation (1 warp / node) -------------
__global__ void agg_kernel(const __half* __restrict__ H, const float* __restrict__ sarr,
                           const float* __restrict__ darr, const float* __restrict__ bias,
                           float* __restrict__ outF, __half* __restrict__ outH, int act) {
    __shared__ float ebuf[8][130];
    __shared__ int   sbuf[8][130];
    int lane = threadIdx.x & 31, ws = threadIdx.x >> 5;
    int node = (blockIdx.x * blockDim.x + threadIdx.x) >> 5;
    if (node >= NN) return;

    int beg = g_rowptr[node], end = g_rowptr[node + 1];
    int deg = end - beg;
    float di = darr[node];
    float* eb = ebuf[ws];
    int*   sb = sbuf[ws];
    int half = lane >> 4, fl = lane & 15;

    float m = -1e30f, den = 0.f;
    bool small = (deg <= 128);

    // pass 1: online softmax; stage sn + raw logit when the node fits in smem
    if (small) {
        for (int j = lane; j < deg; j += 32) {
            int sn = g_col[beg + j];
            float e = __ldg(&sarr[sn]) + di;    // L1-resident (H bypasses L1)
            e = e > 0.f ? e : 0.2f * e;
            sb[j] = sn;
            eb[j] = e;
            float nm = fmaxf(m, e);
            den = den * __expf(m - nm) + __expf(e - nm);
            m = nm;
        }
    } else {
        for (int j = beg + lane; j < end; j += 32) {
            float e = __ldg(&sarr[g_col[j]]) + di;
            e = e > 0.f ? e : 0.2f * e;
            float nm = fmaxf(m, e);
            den = den * __expf(m - nm) + __expf(e - nm);
            m = nm;
        }
    }
    #pragma unroll
    for (int o = 16; o; o >>= 1) {
        float m2 = __shfl_xor_sync(0xffffffffu, m, o);
        float d2 = __shfl_xor_sync(0xffffffffu, den, o);
        float nm = fmaxf(m, m2);
        den = den * __expf(m - nm) + d2 * __expf(m2 - nm);
        m = nm;
    }
    float inv = 1.f / den;

    // pass 2: pair-gather accumulate; acc8 = 8 features per lane, halves merged
    float acc8[8];
    #pragma unroll
    for (int q = 0; q < 8; q++) acc8[q] = 0.f;

    if (small) {
        for (int j = lane; j < deg; j += 32)
            eb[j] = __expf(eb[j] - m) * inv;     // logit -> alpha in place
        if (lane == 0 && (deg & 1)) { eb[deg] = 0.f; sb[deg] = 0; }
        __syncwarp();
        gather_acc2(H, sb, eb, (deg + 1) & ~1, half, fl, acc8);
        __syncwarp();
    } else {
        for (int cb = beg; cb < end; cb += 128) {
            int cn = min(128, end - cb);
            for (int j = lane; j < cn; j += 32) {
                int sn = g_col[cb + j];
                float e = __ldg(&sarr[sn]) + di;
                e = e > 0.f ? e : 0.2f * e;
                sb[j] = sn;
                eb[j] = __expf(e - m) * inv;
            }
            if (lane == 0 && (cn & 1)) { eb[cn] = 0.f; sb[cn] = 0; }
            __syncwarp();
            gather_acc2(H, sb, eb, (cn + 1) & ~1, half, fl, acc8);
            __syncwarp();
        }
    }

    // merge the two edge-halves: lane l and lane l+16 hold same feature slice
    #pragma unroll
    for (int q = 0; q < 8; q++)
        acc8[q] += __shfl_xor_sync(0xffffffffu, acc8[q], 16);

    if (half == 0) {
        float4 b0 = ((const float4*)bias)[fl * 2];
        float4 b1 = ((const float4*)bias)[fl * 2 + 1];
        acc8[0] += b0.x; acc8[1] += b0.y; acc8[2] += b0.z; acc8[3] += b0.w;
        acc8[4] += b1.x; acc8[5] += b1.y; acc8[6] += b1.z; acc8[7] += b1.w;
        if (act) {
            #pragma unroll
            for (int q = 0; q < 8; q++) acc8[q] = 2.f * tanhf(acc8[q]);
            __half2 h0 = __floats2half2_rn(acc8[0], acc8[1]);
            __half2 h1 = __floats2half2_rn(acc8[2], acc8[3]);
            __half2 h2 = __floats2half2_rn(acc8[4], acc8[5]);
            __half2 h3 = __floats2half2_rn(acc8[6], acc8[7]);
            uint4 st;
            st.x = *(unsigned*)&h0; st.y = *(unsigned*)&h1;
            st.z = *(unsigned*)&h2; st.w = *(unsigned*)&h3;
            ((uint4*)(outH + node * 128))[fl] = st;
        } else {
            float4 o0 = make_float4(acc8[0], acc8[1], acc8[2], acc8[3]);
            float4 o1 = make_float4(acc8[4], acc8[5], acc8[6], acc8[7]);
            ((float4*)(outF + node * 128))[fl * 2] = o0;
            ((float4*)(outF + node * 128))[fl * 2 + 1] = o1;
        }
    }
}

// ---------------- launch ------------------------------------------------------
extern "C" void kernel_launch(void* const* d_in, const int* in_sizes, int n_in,
                              void* d_out, int out_size) {
    const float* x   = (const float*)d_in[0];
    const int*   ei  = (const int*)d_in[1];
    const int*   esrc = ei;
    const int*   edst = ei + EE;
    const float* W1  = (const float*)d_in[2];
    const float* a1s = (const float*)d_in[3];
    const float* a1d = (const float*)d_in[4];
    const float* b1  = (const float*)d_in[5];
    const float* W2  = (const float*)d_in[6];
    const float* a2s = (const float*)d_in[7];
    const float* a2d = (const float*)d_in[8];
    const float* b2  = (const float*)d_in[9];
    const float* W3  = (const float*)d_in[10];
    const float* a3s = (const float*)d_in[11];
    const float* a3d = (const float*)d_in[12];
    const float* b3  = (const float*)d_in[13];
    float* out = (float*)d_out;

    float *pS, *pD;
    __half *pA, *pH;
    cudaGetSymbolAddress((void**)&pA, g_bufA);
    cudaGetSymbolAddress((void**)&pH, g_bufH);
    cudaGetSymbolAddress((void**)&pS, g_s);
    cudaGetSymbolAddress((void**)&pD, g_d);

    const int SMEM = (128 * KS + 64 * KS) * 2 + 2 * 128 * 4;   // ~51.7 KB
    cudaFuncSetAttribute(gemm_kernel, cudaFuncAttributeMaxDynamicSharedMemorySize, SMEM);

    // CSR build (once per launch)
    init_count_kernel<<<(NN + 255) / 256, 256>>>();
    hist_kernel<<<(EE + 255) / 256, 256>>>(edst);
    scan_kernel<<<1, 1024>>>();
    scatter_kernel<<<(ET + 255) / 256, 256>>>(esrc, edst);

    // expmap0
    expmap_kernel<<<(NN * 32 + 255) / 256, 256>>>(x);

    int gemm_blocks = (NN + 63) / 64;
    int agg_blocks  = (NN + 7) / 8;

    // layer 1
    gemm_kernel<<<gemm_blocks, 128, SMEM>>>(pA, W1, a1s, a1d);
    agg_kernel<<<agg_blocks, 256>>>(pH, pS, pD, b1, nullptr, pA, 1);
    // layer 2
    gemm_kernel<<<gemm_blocks, 128, SMEM>>>(pA, W2, a2s, a2d);
    agg_kernel<<<agg_blocks, 256>>>(pH, pS, pD, b2, nullptr, pA, 1);
    // layer 3
    gemm_kernel<<<gemm_blocks, 128, SMEM>>>(pA, W3, a3s, a3d);
    agg_kernel<<<agg_blocks, 256>>>(pH, pS, pD, b3, out, nullptr, 0);
}

// round 8
// speedup vs baseline: 1.6853x; 1.0711x over previous
#include <cuda_runtime.h>
#include <cuda_fp16.h>
#include <math.h>

#define NN 50000
#define EE 1600000
#define DD 128
#define ET (EE + NN)
#define SCAN_BLK 98          // ceil(50000 / 512)

// ---------------- scratch (static device globals; no allocation) ------------
__device__ __half g_bufA[NN * DD];   // layer input activations (fp16)
__device__ __half g_bufH[NN * DD];   // h = A @ W (fp16 for the gather)
__device__ float  g_s[NN];           // h . a_src
__device__ float  g_d[NN];           // h . a_dst
__device__ int    g_count[NN];
__device__ int    g_rowptr[NN + 1];
__device__ int    g_cursor[NN];
__device__ int    g_col[ET];         // CSR (by dst) source indices
__device__ int    g_part[SCAN_BLK];  // per-block scan partials

// ---------------- CSR build --------------------------------------------------
__global__ void init_count_kernel() {
    int i = blockIdx.x * blockDim.x + threadIdx.x;
    if (i < NN) g_count[i] = 1;   // self loop
}

__global__ void hist_kernel(const int* __restrict__ dst) {
    int i = blockIdx.x * blockDim.x + threadIdx.x;
    if (i < EE) atomicAdd(&g_count[dst[i]], 1);
}

// phase 1: per-block (512 threads) exclusive scan; writes block total to g_part
__global__ void bscan_kernel() {
    __shared__ int wsum[16];
    int tid = threadIdx.x, lane = tid & 31, wid = tid >> 5;
    int i = blockIdx.x * 512 + tid;
    int v = (i < NN) ? g_count[i] : 0;
    int x = v;
    #pragma unroll
    for (int o = 1; o < 32; o <<= 1) {
        int y = __shfl_up_sync(0xffffffffu, x, o);
        if (lane >= o) x += y;
    }
    if (lane == 31) wsum[wid] = x;
    __syncthreads();
    if (wid == 0 && lane < 16) {
        int w = wsum[lane];
        int xx = w;
        #pragma unroll
        for (int o = 1; o < 16; o <<= 1) {
            int y = __shfl_up_sync(0xffffu, xx, o);
            if (lane >= o) xx += y;
        }
        wsum[lane] = xx - w;
    }
    __syncthreads();
    int incl = x + wsum[wid];
    if (i < NN) g_rowptr[i] = incl - v;        // block-local exclusive
    if (tid == 511) g_part[blockIdx.x] = incl; // block total
}

// phase 2: single-warp scan of the 98 block totals (exclusive, in place)
__global__ void pscan_kernel() {
    int lane = threadIdx.x;
    int base = 0;
    for (int b = 0; b < SCAN_BLK; b += 32) {
        int idx = b + lane;
        int v = (idx < SCAN_BLK) ? g_part[idx] : 0;
        int x = v;
        #pragma unroll
        for (int o = 1; o < 32; o <<= 1) {
            int y = __shfl_up_sync(0xffffffffu, x, o);
            if (lane >= o) x += y;
        }
        if (idx < SCAN_BLK) g_part[idx] = base + x - v;
        int tot = __shfl_sync(0xffffffffu, x, 31);
        base += tot;
        if (b + 32 >= SCAN_BLK && lane == 0) g_rowptr[NN] = base;
    }
}

// phase 3: add block offsets; also fill g_cursor
__global__ void badd_kernel() {
    int i = blockIdx.x * 512 + threadIdx.x;
    if (i < NN) {
        int r = g_rowptr[i] + g_part[blockIdx.x];
        g_rowptr[i] = r;
        g_cursor[i] = r;
    }
}

__global__ void scatter_kernel(const int* __restrict__ src, const int* __restrict__ dst) {
    int i = blockIdx.x * blockDim.x + threadIdx.x;
    if (i >= ET) return;
    int s, t;
    if (i < EE) { s = src[i]; t = dst[i]; }
    else        { s = i - EE; t = s; }
    int pos = atomicAdd(&g_cursor[t], 1);
    g_col[pos] = s;
}

// ---------------- expmap0 (writes fp16 activations) ---------------------------
__global__ void expmap_kernel(const float* __restrict__ x) {
    int gid = blockIdx.x * blockDim.x + threadIdx.x;
    int row = gid >> 5, lane = gid & 31;
    if (row >= NN) return;
    float4 v = ((const float4*)x)[row * 32 + lane];
    float ss = v.x * v.x + v.y * v.y + v.z * v.z + v.w * v.w;
    #pragma unroll
    for (int o = 16; o; o >>= 1) ss += __shfl_xor_sync(0xffffffffu, ss, o);
    float n = sqrtf(ss);
    n = fmaxf(n, 1e-15f);
    float sc = tanhf(n) / n;
    __half2 h0 = __floats2half2_rn(v.x * sc, v.y * sc);
    __half2 h1 = __floats2half2_rn(v.z * sc, v.w * sc);
    uint2 st;
    st.x = *(unsigned int*)&h0;
    st.y = *(unsigned int*)&h1;
    ((uint2*)g_bufA)[row * 32 + lane] = st;
}

// ---------------- tensor-core GEMM: H = A @ W + fused s/d epilogue -----------
#define KS 132   // padded k-stride in halves

__device__ __forceinline__ void mma16816(float* c, unsigned a0, unsigned a1,
                                         unsigned a2, unsigned a3,
                                         unsigned b0, unsigned b1) {
    asm volatile(
        "mma.sync.aligned.m16n8k16.row.col.f32.f16.f16.f32 "
        "{%0,%1,%2,%3}, {%4,%5,%6,%7}, {%8,%9}, {%0,%1,%2,%3};"
        : "+f"(c[0]), "+f"(c[1]), "+f"(c[2]), "+f"(c[3])
        : "r"(a0), "r"(a1), "r"(a2), "r"(a3), "r"(b0), "r"(b1));
}

__global__ void gemm_kernel(const __half* __restrict__ A, const float* __restrict__ W,
                            const float* __restrict__ avs, const float* __restrict__ avd) {
    extern __shared__ char smraw[];
    __half* Wt  = (__half*)smraw;                    // [128][KS]
    __half* As  = Wt + 128 * KS;                     // [64][KS]
    float*  ass = (float*)(As + 64 * KS);            // [128]
    float*  ads = ass + 128;                         // [128]
    int tid = threadIdx.x;
    int row0 = blockIdx.x * 64;

    for (int i = tid; i < 128 * 128; i += 128) {
        int k = i >> 7, n = i & 127;
        Wt[n * KS + k] = __float2half(W[i]);
    }
    for (int i = tid; i < 64 * 32; i += 128) {
        int r = i >> 5, c4 = i & 31;
        int row = row0 + r;
        uint2 v = (row < NN) ? ((const uint2*)A)[row * 32 + c4]
                             : make_uint2(0u, 0u);
        *(uint2*)&As[r * KS + c4 * 4] = v;
    }
    if (tid < 128) { ass[tid] = avs[tid]; ads[tid] = avd[tid]; }
    __syncthreads();

    int w = tid >> 5, lane = tid & 31;
    int gid = lane >> 2, tig = lane & 3;
    int rA = w * 16 + gid;
    int rB = rA + 8;

    float c[16][4];
    #pragma unroll
    for (int nt = 0; nt < 16; nt++)
        #pragma unroll
        for (int j = 0; j < 4; j++) c[nt][j] = 0.f;

    #pragma unroll
    for (int ks = 0; ks < 8; ks++) {
        int k0 = ks * 16;
        unsigned a0 = *(const unsigned*)&As[rA * KS + k0 + 2 * tig];
        unsigned a1 = *(const unsigned*)&As[rB * KS + k0 + 2 * tig];
        unsigned a2 = *(const unsigned*)&As[rA * KS + k0 + 2 * tig + 8];
        unsigned a3 = *(const unsigned*)&As[rB * KS + k0 + 2 * tig + 8];
        #pragma unroll
        for (int nt = 0; nt < 16; nt++) {
            const __half* bp = &Wt[(nt * 8 + gid) * KS + k0 + 2 * tig];
            unsigned b0 = *(const unsigned*)bp;
            unsigned b1 = *(const unsigned*)(bp + 8);
            mma16816(c[nt], a0, a1, a2, a3, b0, b1);
        }
    }

    int rowA = row0 + rA, rowB = row0 + rB;
    float s0 = 0.f, s1 = 0.f, d0 = 0.f, d1 = 0.f;
    #pragma unroll
    for (int nt = 0; nt < 16; nt++) {
        int col = nt * 8 + 2 * tig;
        float2 as2 = *(const float2*)&ass[col];
        float2 ad2 = *(const float2*)&ads[col];
        s0 += c[nt][0] * as2.x + c[nt][1] * as2.y;
        d0 += c[nt][0] * ad2.x + c[nt][1] * ad2.y;
        s1 += c[nt][2] * as2.x + c[nt][3] * as2.y;
        d1 += c[nt][2] * ad2.x + c[nt][3] * ad2.y;
        if (rowA < NN) {
            __half2 h = __floats2half2_rn(c[nt][0], c[nt][1]);
            *(unsigned*)&g_bufH[rowA * 128 + col] = *(unsigned*)&h;
        }
        if (rowB < NN) {
            __half2 h = __floats2half2_rn(c[nt][2], c[nt][3]);
            *(unsigned*)&g_bufH[rowB * 128 + col] = *(unsigned*)&h;
        }
    }
    #pragma unroll
    for (int o = 1; o <= 2; o <<= 1) {
        s0 += __shfl_xor_sync(0xffffffffu, s0, o);
        d0 += __shfl_xor_sync(0xffffffffu, d0, o);
        s1 += __shfl_xor_sync(0xffffffffu, s1, o);
        d1 += __shfl_xor_sync(0xffffffffu, d1, o);
    }
    if (tig == 0) {
        if (rowA < NN) { g_s[rowA] = s0; g_d[rowA] = d0; }
        if (rowB < NN) { g_s[rowB] = s1; g_d[rowB] = d1; }
    }
}

// ---------------- aggregation helpers -----------------------------------------
// pair-gather: 2 edges per warp-iteration, LDG.128, L1-bypass. unroll 4 to keep
// registers <= ~48 so 5 blocks / SM stay resident (occupancy >> MLP here).
__device__ __forceinline__ void gather_acc2(const __half* __restrict__ H,
                                            const int* sb, const float* eb,
                                            int cn, int half, int fl,
                                            float* acc8) {
    int j = 0;
    for (; j + 8 <= cn; j += 8) {        // 4 pairs = 8 edges
        uint4 hv[4];
        float al[4];
        #pragma unroll
        for (int u = 0; u < 4; u++) {
            int idx = j + 2 * u + half;
            int sn = sb[idx];
            al[u] = eb[idx];
            hv[u] = __ldcg(((const uint4*)(H + sn * 128)) + fl);
        }
        #pragma unroll
        for (int u = 0; u < 4; u++) {
            const __half2* p = (const __half2*)&hv[u];
            #pragma unroll
            for (int q = 0; q < 4; q++) {
                float2 f = __half22float2(p[q]);
                acc8[2 * q + 0] = fmaf(al[u], f.x, acc8[2 * q + 0]);
                acc8[2 * q + 1] = fmaf(al[u], f.y, acc8[2 * q + 1]);
            }
        }
    }
    for (; j < cn; j += 2) {             // leftover pairs
        int idx = j + half;
        int sn = sb[idx];
        float al = eb[idx];
        uint4 hv = __ldcg(((const uint4*)(H + sn * 128)) + fl);
        const __half2* p = (const __half2*)&hv;
        #pragma unroll
        for (int q = 0; q < 4; q++) {
            float2 f = __half22float2(p[q]);
            acc8[2 * q + 0] = fmaf(al, f.x, acc8[2 * q + 0]);
            acc8[2 * q + 1] = fmaf(al, f.y, acc8[2 * q + 1]);
        }
    }
}

// ---------------- per-node attention aggregation (1 warp / node) -------------
__global__ void __launch_bounds__(256, 5)
agg_kernel(const __half* __restrict__ H, const float* __restrict__ sarr,
           const float* __restrict__ darr, const float* __restrict__ bias,
           float* __restrict__ outF, __half* __restrict__ outH, int act) {
    __shared__ float ebuf[8][130];
    __shared__ int   sbuf[8][130];
    int lane = threadIdx.x & 31, ws = threadIdx.x >> 5;
    int node = (blockIdx.x * blockDim.x + threadIdx.x) >> 5;
    if (node >= NN) return;

    int beg = g_rowptr[node], end = g_rowptr[node + 1];
    int deg = end - beg;
    float di = darr[node];
    float* eb = ebuf[ws];
    int*   sb = sbuf[ws];
    int half = lane >> 4, fl = lane & 15;

    float m = -1e30f, den = 0.f;
    bool small = (deg <= 128);

    if (small) {
        for (int j = lane; j < deg; j += 32) {
            int sn = g_col[beg + j];
            float e = __ldg(&sarr[sn]) + di;
            e = e > 0.f ? e : 0.2f * e;
            sb[j] = sn;
            eb[j] = e;
            float nm = fmaxf(m, e);
            den = den * __expf(m - nm) + __expf(e - nm);
            m = nm;
        }
    } else {
        for (int j = beg + lane; j < end; j += 32) {
            float e = __ldg(&sarr[g_col[j]]) + di;
            e = e > 0.f ? e : 0.2f * e;
            float nm = fmaxf(m, e);
            den = den * __expf(m - nm) + __expf(e - nm);
            m = nm;
        }
    }
    #pragma unroll
    for (int o = 16; o; o >>= 1) {
        float m2 = __shfl_xor_sync(0xffffffffu, m, o);
        float d2 = __shfl_xor_sync(0xffffffffu, den, o);
        float nm = fmaxf(m, m2);
        den = den * __expf(m - nm) + d2 * __expf(m2 - nm);
        m = nm;
    }
    float inv = 1.f / den;

    float acc8[8];
    #pragma unroll
    for (int q = 0; q < 8; q++) acc8[q] = 0.f;

    if (small) {
        for (int j = lane; j < deg; j += 32)
            eb[j] = __expf(eb[j] - m) * inv;
        if (lane == 0 && (deg & 1)) { eb[deg] = 0.f; sb[deg] = 0; }
        __syncwarp();
        gather_acc2(H, sb, eb, (deg + 1) & ~1, half, fl, acc8);
        __syncwarp();
    } else {
        for (int cb = beg; cb < end; cb += 128) {
            int cn = min(128, end - cb);
            for (int j = lane; j < cn; j += 32) {
                int sn = g_col[cb + j];
                float e = __ldg(&sarr[sn]) + di;
                e = e > 0.f ? e : 0.2f * e;
                sb[j] = sn;
                eb[j] = __expf(e - m) * inv;
            }
            if (lane == 0 && (cn & 1)) { eb[cn] = 0.f; sb[cn] = 0; }
            __syncwarp();
            gather_acc2(H, sb, eb, (cn + 1) & ~1, half, fl, acc8);
            __syncwarp();
        }
    }

    #pragma unroll
    for (int q = 0; q < 8; q++)
        acc8[q] += __shfl_xor_sync(0xffffffffu, acc8[q], 16);

    if (half == 0) {
        float4 b0 = ((const float4*)bias)[fl * 2];
        float4 b1 = ((const float4*)bias)[fl * 2 + 1];
        acc8[0] += b0.x; acc8[1] += b0.y; acc8[2] += b0.z; acc8[3] += b0.w;
        acc8[4] += b1.x; acc8[5] += b1.y; acc8[6] += b1.z; acc8[7] += b1.w;
        if (act) {
            #pragma unroll
            for (int q = 0; q < 8; q++) acc8[q] = 2.f * tanhf(acc8[q]);
            __half2 h0 = __floats2half2_rn(acc8[0], acc8[1]);
            __half2 h1 = __floats2half2_rn(acc8[2], acc8[3]);
            __half2 h2 = __floats2half2_rn(acc8[4], acc8[5]);
            __half2 h3 = __floats2half2_rn(acc8[6], acc8[7]);
            uint4 st;
            st.x = *(unsigned*)&h0; st.y = *(unsigned*)&h1;
            st.z = *(unsigned*)&h2; st.w = *(unsigned*)&h3;
            ((uint4*)(outH + node * 128))[fl] = st;
        } else {
            float4 o0 = make_float4(acc8[0], acc8[1], acc8[2], acc8[3]);
            float4 o1 = make_float4(acc8[4], acc8[5], acc8[6], acc8[7]);
            ((float4*)(outF + node * 128))[fl * 2] = o0;
            ((float4*)(outF + node * 128))[fl * 2 + 1] = o1;
        }
    }
}

// ---------------- launch ------------------------------------------------------
extern "C" void kernel_launch(void* const* d_in, const int* in_sizes, int n_in,
                              void* d_out, int out_size) {
    const float* x   = (const float*)d_in[0];
    const int*   ei  = (const int*)d_in[1];
    const int*   esrc = ei;
    const int*   edst = ei + EE;
    const float* W1  = (const float*)d_in[2];
    const float* a1s = (const float*)d_in[3];
    const float* a1d = (const float*)d_in[4];
    const float* b1  = (const float*)d_in[5];
    const float* W2  = (const float*)d_in[6];
    const float* a2s = (const float*)d_in[7];
    const float* a2d = (const float*)d_in[8];
    const float* b2  = (const float*)d_in[9];
    const float* W3  = (const float*)d_in[10];
    const float* a3s = (const float*)d_in[11];
    const float* a3d = (const float*)d_in[12];
    const float* b3  = (const float*)d_in[13];
    float* out = (float*)d_out;

    float *pS, *pD;
    __half *pA, *pH;
    cudaGetSymbolAddress((void**)&pA, g_bufA);
    cudaGetSymbolAddress((void**)&pH, g_bufH);
    cudaGetSymbolAddress((void**)&pS, g_s);
    cudaGetSymbolAddress((void**)&pD, g_d);

    const int SMEM = (128 * KS + 64 * KS) * 2 + 2 * 128 * 4;   // ~51.7 KB
    cudaFuncSetAttribute(gemm_kernel, cudaFuncAttributeMaxDynamicSharedMemorySize, SMEM);

    // CSR build (once per launch)
    init_count_kernel<<<(NN + 255) / 256, 256>>>();
    hist_kernel<<<(EE + 255) / 256, 256>>>(edst);
    bscan_kernel<<<SCAN_BLK, 512>>>();
    pscan_kernel<<<1, 32>>>();
    badd_kernel<<<SCAN_BLK, 512>>>();
    scatter_kernel<<<(ET + 255) / 256, 256>>>(esrc, edst);

    // expmap0
    expmap_kernel<<<(NN * 32 + 255) / 256, 256>>>(x);

    int gemm_blocks = (NN + 63) / 64;
    int agg_blocks  = (NN + 7) / 8;

    // layer 1
    gemm_kernel<<<gemm_blocks, 128, SMEM>>>(pA, W1, a1s, a1d);
    agg_kernel<<<agg_blocks, 256>>>(pH, pS, pD, b1, nullptr, pA, 1);
    // layer 2
    gemm_kernel<<<gemm_blocks, 128, SMEM>>>(pA, W2, a2s, a2d);
    agg_kernel<<<agg_blocks, 256>>>(pH, pS, pD, b2, nullptr, pA, 1);
    // layer 3
    gemm_kernel<<<gemm_blocks, 128, SMEM>>>(pA, W3, a3s, a3d);
    agg_kernel<<<agg_blocks, 256>>>(pH, pS, pD, b3, out, nullptr, 0);
}